// round 1
// baseline (speedup 1.0000x reference)
#include <cuda_runtime.h>
#include <cstdint>

// ---------------- problem constants ----------------
#define N_NODES 4096
#define FIN     512
#define HID     64
#define HEADS   8
#define FOUT    256

// ---------------- scratch (device globals; no allocation allowed) ----------------
__device__ float g_Wh1[(size_t)HEADS * N_NODES * HID];   // [h][i][d]   8 MB
__device__ float g_h[(size_t)N_NODES * (HEADS * HID)];   // [i][h*64+d] 8 MB
__device__ float g_Wh2[(size_t)N_NODES * FOUT];          // 4 MB
__device__ float g_out2[(size_t)N_NODES * FOUT];         // 4 MB
__device__ float g_s1[HEADS * N_NODES];
__device__ float g_s2[HEADS * N_NODES];
__device__ float g_s2m[HEADS];
__device__ float g_s1b[N_NODES];
__device__ float g_s2b[N_NODES];
__device__ float g_s2mb[1];

// ---------------- fast exp: FMA-pipe only (avoids MUFU bottleneck) ----------------
// exp(x) = 2^(x*log2e); round via magic number, 2^f degree-6 poly, ldexp via bit add.
// Valid for x in ~[-80, 80]; here x <= 0 and > -40. rel err ~2e-7.
__device__ __forceinline__ float fast_exp(float x) {
    float y = x * 1.4426950408889634f;
    float t = y + 12582912.0f;            // 1.5 * 2^23
    int   i = __float_as_int(t);          // low bits hold round(y) (2's complement)
    float f = y - (t - 12582912.0f);      // f in [-0.5, 0.5]
    float p = 1.5403530e-4f;              // 2^f Taylor/minimax
    p = fmaf(p, f, 1.3333558e-3f);
    p = fmaf(p, f, 9.6181291e-3f);
    p = fmaf(p, f, 5.5504109e-2f);
    p = fmaf(p, f, 2.4022651e-1f);
    p = fmaf(p, f, 6.9314718e-1f);
    p = fmaf(p, f, 1.0f);
    return __int_as_float(__float_as_int(p) + (i << 23));
}

__device__ __forceinline__ float lrelu02(float t) {
    return fmaxf(t, 0.2f * t);
}

// ---------------- batched tiled SGEMM: C[b] = A @ B[b] ----------------
// A: [M,K] (shared over batch), B: [b][K,N], C: [b][M,N]. BM=128 BN=64 BK=16.
__global__ __launch_bounds__(256) void gemm_kernel(
    const float* __restrict__ A, const float* __restrict__ B, float* __restrict__ C,
    int M, int N, int K)
{
    __shared__ float Asm[16][132];
    __shared__ float Bsm[16][64];
    int tid = threadIdx.x;
    int bz  = blockIdx.z;
    B += (size_t)bz * K * N;
    C += (size_t)bz * M * N;
    int i0 = blockIdx.x * 128;
    int n0 = blockIdx.y * 64;
    int tr = tid >> 3;        // 0..31
    int tc = tid & 7;         // 0..7

    float acc[4][8];
#pragma unroll
    for (int m = 0; m < 4; m++)
#pragma unroll
        for (int n = 0; n < 8; n++) acc[m][n] = 0.f;

    int ar  = tid >> 2;       // 0..63
    int akq = tid & 3;        // 0..3
    int br  = tid >> 4;       // 0..15
    int bq  = tid & 15;       // 0..15

    for (int k0 = 0; k0 < K; k0 += 16) {
#pragma unroll
        for (int h = 0; h < 2; h++) {
            int r = ar + h * 64;
            float4 v = *(const float4*)&A[(size_t)(i0 + r) * K + k0 + akq * 4];
            Asm[akq * 4 + 0][r] = v.x;
            Asm[akq * 4 + 1][r] = v.y;
            Asm[akq * 4 + 2][r] = v.z;
            Asm[akq * 4 + 3][r] = v.w;
        }
        *(float4*)&Bsm[br][bq * 4] =
            *(const float4*)&B[(size_t)(k0 + br) * N + n0 + bq * 4];
        __syncthreads();
#pragma unroll
        for (int k = 0; k < 16; k++) {
            float4 a4 = *(const float4*)&Asm[k][tr * 4];
            float a[4] = {a4.x, a4.y, a4.z, a4.w};
            float b[8];
            *(float4*)&b[0] = *(const float4*)&Bsm[k][tc * 8];
            *(float4*)&b[4] = *(const float4*)&Bsm[k][tc * 8 + 4];
#pragma unroll
            for (int m = 0; m < 4; m++)
#pragma unroll
                for (int n = 0; n < 8; n++)
                    acc[m][n] = fmaf(a[m], b[n], acc[m][n]);
        }
        __syncthreads();
    }
#pragma unroll
    for (int m = 0; m < 4; m++) {
        int r = i0 + tr * 4 + m;
#pragma unroll
        for (int nq = 0; nq < 2; nq++) {
            float4 v = make_float4(acc[m][nq * 4 + 0], acc[m][nq * 4 + 1],
                                   acc[m][nq * 4 + 2], acc[m][nq * 4 + 3]);
            *(float4*)&C[(size_t)r * N + n0 + tc * 8 + nq * 4] = v;
        }
    }
}

// ---------------- s1/s2 = Wh @ a1, Wh @ a2 (warp per row) ----------------
__global__ __launch_bounds__(256) void scores_kernel(
    const float* __restrict__ Wh, const float* __restrict__ a1,
    const float* __restrict__ a2, float* __restrict__ s1, float* __restrict__ s2,
    int N, int D)
{
    int b = blockIdx.y;
    Wh += (size_t)b * N * D;
    a1 += b * D; a2 += b * D;
    s1 += (size_t)b * N; s2 += (size_t)b * N;
    int warp = threadIdx.x >> 5, lane = threadIdx.x & 31;
    int i = blockIdx.x * 8 + warp;
    const float* row = Wh + (size_t)i * D;
    float v1 = 0.f, v2 = 0.f;
    for (int d = lane; d < D; d += 32) {
        float w = row[d];
        v1 = fmaf(w, a1[d], v1);
        v2 = fmaf(w, a2[d], v2);
    }
#pragma unroll
    for (int o = 16; o > 0; o >>= 1) {
        v1 += __shfl_xor_sync(~0u, v1, o);
        v2 += __shfl_xor_sync(~0u, v2, o);
    }
    if (lane == 0) { s1[i] = v1; s2[i] = v2; }
}

// ---------------- per-batch max over s2 ----------------
__global__ __launch_bounds__(256) void max_kernel(
    const float* __restrict__ s2, float* __restrict__ out, int N)
{
    int b = blockIdx.x;
    s2 += (size_t)b * N;
    __shared__ float red[256];
    float m = -1e30f;
    for (int i = threadIdx.x; i < N; i += 256) m = fmaxf(m, s2[i]);
    red[threadIdx.x] = m;
    __syncthreads();
    for (int s = 128; s > 0; s >>= 1) {
        if (threadIdx.x < s) red[threadIdx.x] = fmaxf(red[threadIdx.x], red[threadIdx.x + s]);
        __syncthreads();
    }
    if (threadIdx.x == 0) out[b] = red[0];
}

// ---------------- fused masked-softmax attention:  out = softmax(e) @ V --------------
// One-pass: per-row upper bound M_i = lrelu(s1_i + max_j s2_j) => exp(e-M) <= 1,
// accumulate numerator and denominator together, normalize at the end.
// Tiles: BM=64 rows, BJ=64 neighbors, BD=64 cols; grid (N/64, D/64, batch).
__global__ __launch_bounds__(256) void attn_kernel(
    const float* __restrict__ V, const float* __restrict__ s1g,
    const float* __restrict__ s2g, const float* __restrict__ s2mg,
    const int* __restrict__ adj, float* __restrict__ out,
    int N, int D, int ldo, int out_bstride, int do_elu)
{
    __shared__ float Psm[64][65];
    __shared__ float Vsm[64][64];
    __shared__ float s1sm[64], Msm[64], denomsm[64];

    int tid = threadIdx.x;
    int z = blockIdx.z;
    V   += (size_t)z * N * D + blockIdx.y * 64;
    s1g += (size_t)z * N;
    s2g += (size_t)z * N;
    out += (size_t)z * out_bstride + blockIdx.y * 64;
    int i0 = blockIdx.x * 64;

    if (tid < 64) {
        float v = s1g[i0 + tid];
        s1sm[tid] = v;
        Msm[tid] = lrelu02(v + s2mg[z]);
    }

    int wj  = tid & 63;   // writer column
    int wrg = tid >> 6;   // 0..3
    int tr  = tid >> 4;   // gemm: 0..15
    int tc  = tid & 15;   // gemm: 0..15
    int vr0 = tid >> 4;   // V loader row
    int vq  = tid & 15;

    float acc[4][4] = {};
    float dacc = 0.f;     // denominator, owned by threads with (tid&3)==0 for row tid>>2
    __syncthreads();

    for (int j0 = 0; j0 < N; j0 += 64) {
        // V tile [64 x 64]
#pragma unroll
        for (int h = 0; h < 4; h++) {
            int r = vr0 + h * 16;
            *(float4*)&Vsm[r][vq * 4] = *(const float4*)&V[(size_t)(j0 + r) * D + vq * 4];
        }
        // P tile
        float s2v = s2g[j0 + wj];
#pragma unroll 4
        for (int rr = 0; rr < 16; rr++) {
            int r = rr * 4 + wrg;
            int a = adj[(i0 + r) * N + j0 + wj];
            float p = 0.f;
            if (a > 0) {
                float t = lrelu02(s1sm[r] + s2v);
                p = fast_exp(t - Msm[r]);
            }
            Psm[r][wj] = p;
        }
        __syncthreads();
        // row sums (denominator)
        {
            int r = tid >> 2, seg = tid & 3;
            float s = 0.f;
#pragma unroll
            for (int k = 0; k < 16; k++) s += Psm[r][seg * 16 + k];
            s += __shfl_xor_sync(~0u, s, 1);
            s += __shfl_xor_sync(~0u, s, 2);
            if (seg == 0) dacc += s;
        }
        // P @ V
#pragma unroll 8
        for (int k = 0; k < 64; k++) {
            float a[4];
#pragma unroll
            for (int m = 0; m < 4; m++) a[m] = Psm[tr * 4 + m][k];
            float4 b = *(const float4*)&Vsm[k][tc * 4];
#pragma unroll
            for (int m = 0; m < 4; m++) {
                acc[m][0] = fmaf(a[m], b.x, acc[m][0]);
                acc[m][1] = fmaf(a[m], b.y, acc[m][1]);
                acc[m][2] = fmaf(a[m], b.z, acc[m][2]);
                acc[m][3] = fmaf(a[m], b.w, acc[m][3]);
            }
        }
        __syncthreads();
    }

    if ((tid & 3) == 0) denomsm[tid >> 2] = dacc;
    __syncthreads();

#pragma unroll
    for (int m = 0; m < 4; m++) {
        int r = tr * 4 + m;
        float dinv = 1.0f / denomsm[r];
        float4 v;
        v.x = acc[m][0] * dinv;
        v.y = acc[m][1] * dinv;
        v.z = acc[m][2] * dinv;
        v.w = acc[m][3] * dinv;
        if (do_elu) {
            v.x = v.x > 0.f ? v.x : expm1f(v.x);
            v.y = v.y > 0.f ? v.y : expm1f(v.y);
            v.z = v.z > 0.f ? v.z : expm1f(v.z);
            v.w = v.w > 0.f ? v.w : expm1f(v.w);
        }
        *(float4*)&out[(size_t)(i0 + r) * ldo + tc * 4] = v;
    }
}

// ---------------- elu + log_softmax over 256 cols (warp per row) ----------------
__global__ __launch_bounds__(256) void final_kernel(
    const float* __restrict__ in, float* __restrict__ out)
{
    int warp = threadIdx.x >> 5, lane = threadIdx.x & 31;
    int row = blockIdx.x * 8 + warp;
    const float* r = in + (size_t)row * FOUT;
    float v[8];
    float mx = -1e30f;
#pragma unroll
    for (int k = 0; k < 8; k++) {
        float x = r[lane + k * 32];
        x = x > 0.f ? x : expm1f(x);
        v[k] = x;
        mx = fmaxf(mx, x);
    }
#pragma unroll
    for (int o = 16; o > 0; o >>= 1) mx = fmaxf(mx, __shfl_xor_sync(~0u, mx, o));
    float s = 0.f;
#pragma unroll
    for (int k = 0; k < 8; k++) s += fast_exp(v[k] - mx);
#pragma unroll
    for (int o = 16; o > 0; o >>= 1) s += __shfl_xor_sync(~0u, s, o);
    float lse = mx + logf(s);
#pragma unroll
    for (int k = 0; k < 8; k++) out[(size_t)row * FOUT + lane + k * 32] = v[k] - lse;
}

// ---------------- launcher ----------------
extern "C" void kernel_launch(void* const* d_in, const int* in_sizes, int n_in,
                              void* d_out, int out_size)
{
    const float* x        = (const float*)d_in[0];
    const int*   adj      = (const int*)  d_in[1];
    const float* W_heads  = (const float*)d_in[2];
    const float* a1_heads = (const float*)d_in[3];
    const float* a2_heads = (const float*)d_in[4];
    const float* W_out    = (const float*)d_in[5];
    const float* a1_out   = (const float*)d_in[6];
    const float* a2_out   = (const float*)d_in[7];
    float* out = (float*)d_out;

    float *Wh1, *hbuf, *Wh2, *out2, *s1, *s2, *s2m, *s1b, *s2b, *s2mb;
    cudaGetSymbolAddress((void**)&Wh1,  g_Wh1);
    cudaGetSymbolAddress((void**)&hbuf, g_h);
    cudaGetSymbolAddress((void**)&Wh2,  g_Wh2);
    cudaGetSymbolAddress((void**)&out2, g_out2);
    cudaGetSymbolAddress((void**)&s1,   g_s1);
    cudaGetSymbolAddress((void**)&s2,   g_s2);
    cudaGetSymbolAddress((void**)&s2m,  g_s2m);
    cudaGetSymbolAddress((void**)&s1b,  g_s1b);
    cudaGetSymbolAddress((void**)&s2b,  g_s2b);
    cudaGetSymbolAddress((void**)&s2mb, g_s2mb);

    // ---- layer 1 ----
    gemm_kernel<<<dim3(N_NODES / 128, 1, HEADS), 256>>>(x, W_heads, Wh1, N_NODES, HID, FIN);
    scores_kernel<<<dim3(N_NODES / 8, HEADS), 256>>>(Wh1, a1_heads, a2_heads, s1, s2, N_NODES, HID);
    max_kernel<<<HEADS, 256>>>(s2, s2m, N_NODES);
    attn_kernel<<<dim3(N_NODES / 64, 1, HEADS), 256>>>(
        Wh1, s1, s2, s2m, adj, hbuf, N_NODES, HID, HEADS * HID, HID, 1);

    // ---- layer 2 ----
    gemm_kernel<<<dim3(N_NODES / 128, FOUT / 64, 1), 256>>>(hbuf, W_out, Wh2, N_NODES, FOUT, FIN);
    scores_kernel<<<dim3(N_NODES / 8, 1), 256>>>(Wh2, a1_out, a2_out, s1b, s2b, N_NODES, FOUT);
    max_kernel<<<1, 256>>>(s2b, s2mb, N_NODES);
    attn_kernel<<<dim3(N_NODES / 64, FOUT / 64, 1), 256>>>(
        Wh2, s1b, s2b, s2mb, adj, out2, N_NODES, FOUT, FOUT, 0, 0);

    // ---- elu + log_softmax ----
    final_kernel<<<N_NODES / 8, 256>>>(out2, out);
}

// round 3
// speedup vs baseline: 1.7700x; 1.7700x over previous
#include <cuda_runtime.h>
#include <cstdint>

// ---------------- problem constants ----------------
#define N_NODES 4096
#define FIN     512
#define HID     64
#define HEADS   8
#define FOUT    256

// ---------------- scratch (device globals; no allocation allowed) ----------------
__device__ float    g_Wh1[(size_t)HEADS * N_NODES * HID];   // [h][i][d]   8 MB
__device__ float    g_h[(size_t)N_NODES * (HEADS * HID)];   // [i][h*64+d] 8 MB
__device__ float    g_Wh2[(size_t)N_NODES * FOUT];          // 4 MB
__device__ float    g_out2[(size_t)N_NODES * FOUT];         // 4 MB
__device__ uint32_t g_adjbits[(size_t)N_NODES * (N_NODES / 32)];  // 2 MB bitmask
__device__ float    g_s1[HEADS * N_NODES];
__device__ float    g_s2[HEADS * N_NODES];
__device__ float    g_s2m[HEADS];
__device__ float    g_s1b[N_NODES];
__device__ float    g_s2b[N_NODES];
__device__ float    g_s2mb[1];

// ---------------- small PTX helpers ----------------
__device__ __forceinline__ uint32_t smem_u32(const void* p) {
    uint32_t a;
    asm("{ .reg .u64 t; cvta.to.shared.u64 t, %1; cvt.u32.u64 %0, t; }" : "=r"(a) : "l"(p));
    return a;
}
#define CP_ASYNC16(dst, src) \
    asm volatile("cp.async.cg.shared.global [%0], [%1], 16;" :: "r"(dst), "l"(src) : "memory")
#define CP_COMMIT() asm volatile("cp.async.commit_group;" ::: "memory")
#define CP_WAIT0()  asm volatile("cp.async.wait_group 0;" ::: "memory")

// mma.sync m16n8k8 tf32 (A row-major, B col-major), D += A*B
__device__ __forceinline__ void mma16n8k8(float* d, const float* a, float b0, float b1) {
    asm volatile(
        "mma.sync.aligned.m16n8k8.row.col.f32.tf32.tf32.f32 "
        "{%0,%1,%2,%3}, {%4,%5,%6,%7}, {%8,%9}, {%0,%1,%2,%3};"
        : "+f"(d[0]), "+f"(d[1]), "+f"(d[2]), "+f"(d[3])
        : "r"(__float_as_uint(a[0])), "r"(__float_as_uint(a[1])),
          "r"(__float_as_uint(a[2])), "r"(__float_as_uint(a[3])),
          "r"(__float_as_uint(b0)),   "r"(__float_as_uint(b1)));
}

// ---------------- fast exp: FMA-pipe only (avoids MUFU bottleneck) ----------------
__device__ __forceinline__ float fast_exp(float x) {
    float y = x * 1.4426950408889634f;
    float t = y + 12582912.0f;            // 1.5 * 2^23
    int   i = __float_as_int(t);
    float f = y - (t - 12582912.0f);
    float p = 1.5403530e-4f;
    p = fmaf(p, f, 1.3333558e-3f);
    p = fmaf(p, f, 9.6181291e-3f);
    p = fmaf(p, f, 5.5504109e-2f);
    p = fmaf(p, f, 2.4022651e-1f);
    p = fmaf(p, f, 6.9314718e-1f);
    p = fmaf(p, f, 1.0f);
    return __int_as_float(__float_as_int(p) + (i << 23));
}
__device__ __forceinline__ float lrelu02(float t) { return fmaxf(t, 0.2f * t); }
__device__ __forceinline__ float elu1(float x) { return x > 0.f ? x : expm1f(x); }

// ---------------- pack adj into row-major bitmask ----------------
__global__ __launch_bounds__(256) void pack_adj(const int* __restrict__ adj,
                                                uint32_t* __restrict__ bits) {
    int w = blockIdx.x * 256 + threadIdx.x;          // word index
    const int4* src = (const int4*)(adj + (size_t)w * 32);
    uint32_t m = 0;
#pragma unroll
    for (int q = 0; q < 8; q++) {
        int4 a = src[q];
        m |= (uint32_t)(a.x > 0) << (q * 4 + 0);
        m |= (uint32_t)(a.y > 0) << (q * 4 + 1);
        m |= (uint32_t)(a.z > 0) << (q * 4 + 2);
        m |= (uint32_t)(a.w > 0) << (q * 4 + 3);
    }
    bits[w] = m;
}

// =================== fused attention with tf32 mma.sync P@V ===================
// Block: 256 thr (8 warps), 128 i-rows, CHUNK output cols. Warp w owns rows
// [i0+16w, i0+16w+16) and ALL CHUNK cols. Loop over 64-j tiles:
//   - P values (exp of masked leaky-relu scores) computed straight into the
//     m16n8k8 A-fragment registers (no smem round trip)
//   - V tile staged global->smem via cp.async (padded stride, conflict-free)
//   - D accumulated in registers via mma.sync tf32.
// One-pass softmax: M_i = lrelu(s1_i + max_j s2_j) upper bound; denominator
// accumulated in exact fp32 alongside.
template<int D, int CHUNK, int LDO, int DO_ELU>
__global__ void __launch_bounds__(256) attn_mma(
    const float* __restrict__ V, const float* __restrict__ s1g,
    const float* __restrict__ s2g, const float* __restrict__ s2mg,
    const uint32_t* __restrict__ adjb, float* __restrict__ out)
{
    constexpr int NFRAG = CHUNK / 8;
    constexpr int SV = CHUNK + 8;        // smem row stride (== 8 mod 32)
    constexpr int T = N_NODES / 64;

    __shared__ float vsm[64 * SV];

    int tid = threadIdx.x, wid = tid >> 5, lane = tid & 31;
    int g = lane >> 2, c = lane & 3;
    int z = blockIdx.z;
    int d0 = blockIdx.y * CHUNK;
    int outc = z * CHUNK + d0;           // layer1: z*64 (d0=0); layer2: d0 (z=0)

    V   += (size_t)z * N_NODES * D + d0;
    s1g += (size_t)z * N_NODES;
    s2g += (size_t)z * N_NODES;

    int i0 = blockIdx.x * 128;
    int r0 = i0 + wid * 16 + g;
    float s1a = s1g[r0], s1b = s1g[r0 + 8];
    float s2max = s2mg[z];
    float Ma = lrelu02(s1a + s2max), Mb = lrelu02(s1b + s2max);
    const uint2* adjrow0 = (const uint2*)(adjb + (size_t)r0 * (N_NODES / 32));
    const uint2* adjrow1 = (const uint2*)(adjb + (size_t)(r0 + 8) * (N_NODES / 32));

    float acc[NFRAG][4];
#pragma unroll
    for (int f = 0; f < NFRAG; f++)
#pragma unroll
        for (int q = 0; q < 4; q++) acc[f][q] = 0.f;
    float aP[8][4];
    float dacc0 = 0.f, dacc1 = 0.f;

    uint32_t vbase = smem_u32(vsm);

    // ---- issue cp.async for V tile at j0 ----
    auto issueV = [&](int j0) {
#pragma unroll
        for (int u = 0; u < (64 * CHUNK / 4) / 256; u++) {
            int idx = tid + 256 * u;                     // float4 index
            int j = idx / (CHUNK / 4);
            int cc = idx % (CHUNK / 4);
            uint32_t dst = vbase + (uint32_t)(j * SV + cc * 4) * 4;
            const float* src = V + (size_t)(j0 + j) * D + cc * 4;
            CP_ASYNC16(dst, src);
        }
        CP_COMMIT();
    };

    // ---- compute P for tile j0 into A-fragment registers ----
    auto computeP = [&](int j0) {
        float s2lo = s2g[j0 + lane];
        float s2hi = s2g[j0 + 32 + lane];
        uint2 w0 = adjrow0[j0 >> 6];
        uint2 w1 = adjrow1[j0 >> 6];
        unsigned long long b0 = (unsigned long long)w0.x | ((unsigned long long)w0.y << 32);
        unsigned long long b1 = (unsigned long long)w1.x | ((unsigned long long)w1.y << 32);
#pragma unroll
        for (int t = 0; t < 8; t++) {
            int idx = 8 * t + c;
            float vsel = (t < 4) ? s2lo : s2hi;
            float s2A = __shfl_sync(~0u, vsel, idx & 31);
            float s2B = __shfl_sync(~0u, vsel, (idx + 4) & 31);
            float p0 = ((b0 >> idx) & 1ULL)       ? fast_exp(lrelu02(s1a + s2A) - Ma) : 0.f;
            float p1 = ((b1 >> idx) & 1ULL)       ? fast_exp(lrelu02(s1b + s2A) - Mb) : 0.f;
            float p2 = ((b0 >> (idx + 4)) & 1ULL) ? fast_exp(lrelu02(s1a + s2B) - Ma) : 0.f;
            float p3 = ((b1 >> (idx + 4)) & 1ULL) ? fast_exp(lrelu02(s1b + s2B) - Mb) : 0.f;
            dacc0 += p0 + p2;
            dacc1 += p1 + p3;
            aP[t][0] = p0; aP[t][1] = p1; aP[t][2] = p2; aP[t][3] = p3;
        }
    };

    issueV(0);
    computeP(0);

    for (int t = 0; t < T; t++) {
        CP_WAIT0();
        __syncthreads();
#pragma unroll
        for (int f = 0; f < NFRAG; f++) {
#pragma unroll
            for (int ks = 0; ks < 8; ks++) {
                float b0v = vsm[(8 * ks + c) * SV + 8 * f + g];
                float b1v = vsm[(8 * ks + c + 4) * SV + 8 * f + g];
                mma16n8k8(acc[f], aP[ks], b0v, b1v);
            }
        }
        __syncthreads();
        if (t + 1 < T) {
            issueV((t + 1) * 64);
            computeP((t + 1) * 64);
        }
    }

    // denominator: reduce over the 4 lanes sharing a row (c = 0..3)
    dacc0 += __shfl_xor_sync(~0u, dacc0, 1);
    dacc0 += __shfl_xor_sync(~0u, dacc0, 2);
    dacc1 += __shfl_xor_sync(~0u, dacc1, 1);
    dacc1 += __shfl_xor_sync(~0u, dacc1, 2);
    float dinv0 = 1.0f / dacc0;
    float dinv1 = 1.0f / dacc1;

    float* row0 = out + (size_t)r0 * LDO + outc;
    float* row1 = row0 + 8 * LDO;
#pragma unroll
    for (int f = 0; f < NFRAG; f++) {
        int col = 8 * f + 2 * c;
        float2 v0, v1;
        v0.x = acc[f][0] * dinv0; v0.y = acc[f][1] * dinv0;
        v1.x = acc[f][2] * dinv1; v1.y = acc[f][3] * dinv1;
        if (DO_ELU) {
            v0.x = elu1(v0.x); v0.y = elu1(v0.y);
            v1.x = elu1(v1.x); v1.y = elu1(v1.y);
        }
        *(float2*)&row0[col] = v0;
        *(float2*)&row1[col] = v1;
    }
}

// ---------------- batched tiled SGEMM: C[b] = A @ B[b] ----------------
__global__ __launch_bounds__(256) void gemm_kernel(
    const float* __restrict__ A, const float* __restrict__ B, float* __restrict__ C,
    int M, int N, int K)
{
    __shared__ float Asm[16][132];
    __shared__ float Bsm[16][64];
    int tid = threadIdx.x;
    int bz  = blockIdx.z;
    B += (size_t)bz * K * N;
    C += (size_t)bz * M * N;
    int i0 = blockIdx.x * 128;
    int n0 = blockIdx.y * 64;
    int tr = tid >> 3;
    int tc = tid & 7;

    float acc[4][8];
#pragma unroll
    for (int m = 0; m < 4; m++)
#pragma unroll
        for (int n = 0; n < 8; n++) acc[m][n] = 0.f;

    int ar  = tid >> 2;
    int akq = tid & 3;
    int br  = tid >> 4;
    int bq  = tid & 15;

    for (int k0 = 0; k0 < K; k0 += 16) {
#pragma unroll
        for (int h = 0; h < 2; h++) {
            int rr = ar + h * 64;
            float4 v = *(const float4*)&A[(size_t)(i0 + rr) * K + k0 + akq * 4];
            Asm[akq * 4 + 0][rr] = v.x;
            Asm[akq * 4 + 1][rr] = v.y;
            Asm[akq * 4 + 2][rr] = v.z;
            Asm[akq * 4 + 3][rr] = v.w;
        }
        *(float4*)&Bsm[br][bq * 4] =
            *(const float4*)&B[(size_t)(k0 + br) * N + n0 + bq * 4];
        __syncthreads();
#pragma unroll
        for (int k = 0; k < 16; k++) {
            float4 a4 = *(const float4*)&Asm[k][tr * 4];
            float a[4] = {a4.x, a4.y, a4.z, a4.w};
            float b[8];
            *(float4*)&b[0] = *(const float4*)&Bsm[k][tc * 8];
            *(float4*)&b[4] = *(const float4*)&Bsm[k][tc * 8 + 4];
#pragma unroll
            for (int m = 0; m < 4; m++)
#pragma unroll
                for (int n = 0; n < 8; n++)
                    acc[m][n] = fmaf(a[m], b[n], acc[m][n]);
        }
        __syncthreads();
    }
#pragma unroll
    for (int m = 0; m < 4; m++) {
        int rr = i0 + tr * 4 + m;
#pragma unroll
        for (int nq = 0; nq < 2; nq++) {
            float4 v = make_float4(acc[m][nq * 4 + 0], acc[m][nq * 4 + 1],
                                   acc[m][nq * 4 + 2], acc[m][nq * 4 + 3]);
            *(float4*)&C[(size_t)rr * N + n0 + tc * 8 + nq * 4] = v;
        }
    }
}

// ---------------- s1/s2 = Wh @ a1, Wh @ a2 (warp per row) ----------------
__global__ __launch_bounds__(256) void scores_kernel(
    const float* __restrict__ Wh, const float* __restrict__ a1,
    const float* __restrict__ a2, float* __restrict__ s1, float* __restrict__ s2,
    int N, int Dd)
{
    int b = blockIdx.y;
    Wh += (size_t)b * N * Dd;
    a1 += b * Dd; a2 += b * Dd;
    s1 += (size_t)b * N; s2 += (size_t)b * N;
    int warp = threadIdx.x >> 5, lane = threadIdx.x & 31;
    int i = blockIdx.x * 8 + warp;
    const float* row = Wh + (size_t)i * Dd;
    float v1 = 0.f, v2 = 0.f;
    for (int d = lane; d < Dd; d += 32) {
        float w = row[d];
        v1 = fmaf(w, a1[d], v1);
        v2 = fmaf(w, a2[d], v2);
    }
#pragma unroll
    for (int o = 16; o > 0; o >>= 1) {
        v1 += __shfl_xor_sync(~0u, v1, o);
        v2 += __shfl_xor_sync(~0u, v2, o);
    }
    if (lane == 0) { s1[i] = v1; s2[i] = v2; }
}

// ---------------- per-batch max over s2 ----------------
__global__ __launch_bounds__(256) void max_kernel(
    const float* __restrict__ s2, float* __restrict__ out, int N)
{
    int b = blockIdx.x;
    s2 += (size_t)b * N;
    __shared__ float red[256];
    float m = -1e30f;
    for (int i = threadIdx.x; i < N; i += 256) m = fmaxf(m, s2[i]);
    red[threadIdx.x] = m;
    __syncthreads();
    for (int s = 128; s > 0; s >>= 1) {
        if (threadIdx.x < s) red[threadIdx.x] = fmaxf(red[threadIdx.x], red[threadIdx.x + s]);
        __syncthreads();
    }
    if (threadIdx.x == 0) out[b] = red[0];
}

// ---------------- elu + log_softmax over 256 cols (warp per row) ----------------
__global__ __launch_bounds__(256) void final_kernel(
    const float* __restrict__ in, float* __restrict__ out)
{
    int warp = threadIdx.x >> 5, lane = threadIdx.x & 31;
    int row = blockIdx.x * 8 + warp;
    const float* r = in + (size_t)row * FOUT;
    float v[8];
    float mx = -1e30f;
#pragma unroll
    for (int k = 0; k < 8; k++) {
        float x = r[lane + k * 32];
        x = elu1(x);
        v[k] = x;
        mx = fmaxf(mx, x);
    }
#pragma unroll
    for (int o = 16; o > 0; o >>= 1) mx = fmaxf(mx, __shfl_xor_sync(~0u, mx, o));
    float s = 0.f;
#pragma unroll
    for (int k = 0; k < 8; k++) s += fast_exp(v[k] - mx);
#pragma unroll
    for (int o = 16; o > 0; o >>= 1) s += __shfl_xor_sync(~0u, s, o);
    float lse = mx + logf(s);
#pragma unroll
    for (int k = 0; k < 8; k++) out[(size_t)row * FOUT + lane + k * 32] = v[k] - lse;
}

// ---------------- launcher ----------------
extern "C" void kernel_launch(void* const* d_in, const int* in_sizes, int n_in,
                              void* d_out, int out_size)
{
    const float* x        = (const float*)d_in[0];
    const int*   adj      = (const int*)  d_in[1];
    const float* W_heads  = (const float*)d_in[2];
    const float* a1_heads = (const float*)d_in[3];
    const float* a2_heads = (const float*)d_in[4];
    const float* W_out    = (const float*)d_in[5];
    const float* a1_out   = (const float*)d_in[6];
    const float* a2_out   = (const float*)d_in[7];
    float* out = (float*)d_out;

    float *Wh1, *hbuf, *Wh2, *out2, *s1, *s2, *s2m, *s1b, *s2b, *s2mb;
    uint32_t* adjb;
    cudaGetSymbolAddress((void**)&Wh1,  g_Wh1);
    cudaGetSymbolAddress((void**)&hbuf, g_h);
    cudaGetSymbolAddress((void**)&Wh2,  g_Wh2);
    cudaGetSymbolAddress((void**)&out2, g_out2);
    cudaGetSymbolAddress((void**)&adjb, g_adjbits);
    cudaGetSymbolAddress((void**)&s1,   g_s1);
    cudaGetSymbolAddress((void**)&s2,   g_s2);
    cudaGetSymbolAddress((void**)&s2m,  g_s2m);
    cudaGetSymbolAddress((void**)&s1b,  g_s1b);
    cudaGetSymbolAddress((void**)&s2b,  g_s2b);
    cudaGetSymbolAddress((void**)&s2mb, g_s2mb);

    // ---- shared prep ----
    pack_adj<<<(N_NODES * (N_NODES / 32)) / 256, 256>>>(adj, adjb);

    // ---- layer 1 ----
    gemm_kernel<<<dim3(N_NODES / 128, 1, HEADS), 256>>>(x, W_heads, Wh1, N_NODES, HID, FIN);
    scores_kernel<<<dim3(N_NODES / 8, HEADS), 256>>>(Wh1, a1_heads, a2_heads, s1, s2, N_NODES, HID);
    max_kernel<<<HEADS, 256>>>(s2, s2m, N_NODES);
    attn_mma<HID, 64, HEADS * HID, 1><<<dim3(N_NODES / 128, 1, HEADS), 256>>>(
        Wh1, s1, s2, s2m, adjb, hbuf);

    // ---- layer 2 ----
    gemm_kernel<<<dim3(N_NODES / 128, FOUT / 64, 1), 256>>>(hbuf, W_out, Wh2, N_NODES, FOUT, FIN);
    scores_kernel<<<dim3(N_NODES / 8, 1), 256>>>(Wh2, a1_out, a2_out, s1b, s2b, N_NODES, FOUT);
    max_kernel<<<1, 256>>>(s2b, s2mb, N_NODES);
    attn_mma<FOUT, 128, FOUT, 0><<<dim3(N_NODES / 128, 2, 1), 256>>>(
        Wh2, s1b, s2b, s2mb, adjb, out2);

    // ---- elu + log_softmax ----
    final_kernel<<<N_NODES / 8, 256>>>(out2, out);
}

// round 4
// speedup vs baseline: 1.7800x; 1.0057x over previous
#include <cuda_runtime.h>
#include <cstdint>

// ---------------- problem constants ----------------
#define N_NODES 4096
#define FIN     512
#define HID     64
#define HEADS   8
#define FOUT    256

// ---------------- scratch (device globals; no allocation allowed) ----------------
__device__ float    g_Wh1[(size_t)HEADS * N_NODES * HID];   // [h][i][d]   8 MB
__device__ float    g_h[(size_t)N_NODES * (HEADS * HID)];   // [i][h*64+d] 8 MB
__device__ float    g_Wh2[(size_t)N_NODES * FOUT];          // 4 MB
__device__ float    g_out2[(size_t)N_NODES * FOUT];         // 4 MB
__device__ uint32_t g_adjbits[(size_t)N_NODES * (N_NODES / 32)];  // 2 MB bitmask
__device__ float    g_s1[HEADS * N_NODES];
__device__ float    g_s2[HEADS * N_NODES];
__device__ float    g_s2m[HEADS];
__device__ float    g_s1b[N_NODES];
__device__ float    g_s2b[N_NODES];
__device__ float    g_s2mb[1];

// ---------------- small PTX helpers ----------------
__device__ __forceinline__ uint32_t smem_u32(const void* p) {
    uint32_t a;
    asm("{ .reg .u64 t; cvta.to.shared.u64 t, %1; cvt.u32.u64 %0, t; }" : "=r"(a) : "l"(p));
    return a;
}
#define CP_ASYNC16(dst, src) \
    asm volatile("cp.async.cg.shared.global [%0], [%1], 16;" :: "r"(dst), "l"(src) : "memory")
#define CP_COMMIT() asm volatile("cp.async.commit_group;" ::: "memory")
#define CP_WAIT0()  asm volatile("cp.async.wait_group 0;" ::: "memory")

// mma.sync m16n8k8 tf32 (A row-major, B col-major), D += A*B
__device__ __forceinline__ void mma16n8k8(float* d, const float* a, float b0, float b1) {
    asm volatile(
        "mma.sync.aligned.m16n8k8.row.col.f32.tf32.tf32.f32 "
        "{%0,%1,%2,%3}, {%4,%5,%6,%7}, {%8,%9}, {%0,%1,%2,%3};"
        : "+f"(d[0]), "+f"(d[1]), "+f"(d[2]), "+f"(d[3])
        : "r"(__float_as_uint(a[0])), "r"(__float_as_uint(a[1])),
          "r"(__float_as_uint(a[2])), "r"(__float_as_uint(a[3])),
          "r"(__float_as_uint(b0)),   "r"(__float_as_uint(b1)));
}

// ---------------- fast exp: FMA-pipe only (avoids MUFU bottleneck) ----------------
__device__ __forceinline__ float fast_exp(float x) {
    float y = x * 1.4426950408889634f;
    float t = y + 12582912.0f;            // 1.5 * 2^23
    int   i = __float_as_int(t);
    float f = y - (t - 12582912.0f);
    float p = 1.5403530e-4f;
    p = fmaf(p, f, 1.3333558e-3f);
    p = fmaf(p, f, 9.6181291e-3f);
    p = fmaf(p, f, 5.5504109e-2f);
    p = fmaf(p, f, 2.4022651e-1f);
    p = fmaf(p, f, 6.9314718e-1f);
    p = fmaf(p, f, 1.0f);
    return __int_as_float(__float_as_int(p) + (i << 23));
}
__device__ __forceinline__ float lrelu02(float t) { return fmaxf(t, 0.2f * t); }
__device__ __forceinline__ float elu1(float x) { return x > 0.f ? x : expm1f(x); }

// ---------------- pack adj into row-major bitmask ----------------
__global__ __launch_bounds__(256) void pack_adj(const int* __restrict__ adj,
                                                uint32_t* __restrict__ bits) {
    int w = blockIdx.x * 256 + threadIdx.x;          // word index
    const int4* src = (const int4*)(adj + (size_t)w * 32);
    uint32_t m = 0;
#pragma unroll
    for (int q = 0; q < 8; q++) {
        int4 a = src[q];
        m |= (uint32_t)(a.x > 0) << (q * 4 + 0);
        m |= (uint32_t)(a.y > 0) << (q * 4 + 1);
        m |= (uint32_t)(a.z > 0) << (q * 4 + 2);
        m |= (uint32_t)(a.w > 0) << (q * 4 + 3);
    }
    bits[w] = m;
}

// =================== fused attention with tf32 mma.sync P@V ===================
// Block: 256 thr (8 warps), 128 i-rows, CHUNK output cols. Warp w owns rows
// [i0+16w, i0+16w+16) and ALL CHUNK cols. Loop over 64-j tiles:
//   - P values (exp of masked leaky-relu scores) computed straight into the
//     m16n8k8 A-fragment registers (no smem round trip)
//   - V tile staged global->smem via cp.async (padded stride, conflict-free)
//   - D accumulated in registers via mma.sync tf32.
// One-pass softmax: M_i = lrelu(s1_i + max_j s2_j) upper bound; denominator
// accumulated in exact fp32 alongside.
template<int D, int CHUNK, int LDO, int DO_ELU>
__global__ void __launch_bounds__(256) attn_mma(
    const float* __restrict__ V, const float* __restrict__ s1g,
    const float* __restrict__ s2g, const float* __restrict__ s2mg,
    const uint32_t* __restrict__ adjb, float* __restrict__ out)
{
    constexpr int NFRAG = CHUNK / 8;
    constexpr int SV = CHUNK + 8;        // smem row stride (== 8 mod 32)
    constexpr int T = N_NODES / 64;

    __shared__ float vsm[64 * SV];

    int tid = threadIdx.x, wid = tid >> 5, lane = tid & 31;
    int g = lane >> 2, c = lane & 3;
    int z = blockIdx.z;
    int d0 = blockIdx.y * CHUNK;
    int outc = z * CHUNK + d0;           // layer1: z*64 (d0=0); layer2: d0 (z=0)

    V   += (size_t)z * N_NODES * D + d0;
    s1g += (size_t)z * N_NODES;
    s2g += (size_t)z * N_NODES;

    int i0 = blockIdx.x * 128;
    int r0 = i0 + wid * 16 + g;
    float s1a = s1g[r0], s1b = s1g[r0 + 8];
    float s2max = s2mg[z];
    float Ma = lrelu02(s1a + s2max), Mb = lrelu02(s1b + s2max);
    const uint2* adjrow0 = (const uint2*)(adjb + (size_t)r0 * (N_NODES / 32));
    const uint2* adjrow1 = (const uint2*)(adjb + (size_t)(r0 + 8) * (N_NODES / 32));

    float acc[NFRAG][4];
#pragma unroll
    for (int f = 0; f < NFRAG; f++)
#pragma unroll
        for (int q = 0; q < 4; q++) acc[f][q] = 0.f;
    float aP[8][4];
    float dacc0 = 0.f, dacc1 = 0.f;

    uint32_t vbase = smem_u32(vsm);

    // ---- issue cp.async for V tile at j0 ----
    auto issueV = [&](int j0) {
#pragma unroll
        for (int u = 0; u < (64 * CHUNK / 4) / 256; u++) {
            int idx = tid + 256 * u;                     // float4 index
            int j = idx / (CHUNK / 4);
            int cc = idx % (CHUNK / 4);
            uint32_t dst = vbase + (uint32_t)(j * SV + cc * 4) * 4;
            const float* src = V + (size_t)(j0 + j) * D + cc * 4;
            CP_ASYNC16(dst, src);
        }
        CP_COMMIT();
    };

    // ---- compute P for tile j0 into A-fragment registers ----
    auto computeP = [&](int j0) {
        float s2lo = s2g[j0 + lane];
        float s2hi = s2g[j0 + 32 + lane];
        uint2 w0 = adjrow0[j0 >> 6];
        uint2 w1 = adjrow1[j0 >> 6];
        unsigned long long b0 = (unsigned long long)w0.x | ((unsigned long long)w0.y << 32);
        unsigned long long b1 = (unsigned long long)w1.x | ((unsigned long long)w1.y << 32);
#pragma unroll
        for (int t = 0; t < 8; t++) {
            int idx = 8 * t + c;
            float vsel = (t < 4) ? s2lo : s2hi;
            float s2A = __shfl_sync(~0u, vsel, idx & 31);
            float s2B = __shfl_sync(~0u, vsel, (idx + 4) & 31);
            float p0 = ((b0 >> idx) & 1ULL)       ? fast_exp(lrelu02(s1a + s2A) - Ma) : 0.f;
            float p1 = ((b1 >> idx) & 1ULL)       ? fast_exp(lrelu02(s1b + s2A) - Mb) : 0.f;
            float p2 = ((b0 >> (idx + 4)) & 1ULL) ? fast_exp(lrelu02(s1a + s2B) - Ma) : 0.f;
            float p3 = ((b1 >> (idx + 4)) & 1ULL) ? fast_exp(lrelu02(s1b + s2B) - Mb) : 0.f;
            dacc0 += p0 + p2;
            dacc1 += p1 + p3;
            aP[t][0] = p0; aP[t][1] = p1; aP[t][2] = p2; aP[t][3] = p3;
        }
    };

    issueV(0);
    computeP(0);

    for (int t = 0; t < T; t++) {
        CP_WAIT0();
        __syncthreads();
#pragma unroll
        for (int f = 0; f < NFRAG; f++) {
#pragma unroll
            for (int ks = 0; ks < 8; ks++) {
                float b0v = vsm[(8 * ks + c) * SV + 8 * f + g];
                float b1v = vsm[(8 * ks + c + 4) * SV + 8 * f + g];
                mma16n8k8(acc[f], aP[ks], b0v, b1v);
            }
        }
        __syncthreads();
        if (t + 1 < T) {
            issueV((t + 1) * 64);
            computeP((t + 1) * 64);
        }
    }

    // denominator: reduce over the 4 lanes sharing a row (c = 0..3)
    dacc0 += __shfl_xor_sync(~0u, dacc0, 1);
    dacc0 += __shfl_xor_sync(~0u, dacc0, 2);
    dacc1 += __shfl_xor_sync(~0u, dacc1, 1);
    dacc1 += __shfl_xor_sync(~0u, dacc1, 2);
    float dinv0 = 1.0f / dacc0;
    float dinv1 = 1.0f / dacc1;

    float* row0 = out + (size_t)r0 * LDO + outc;
    float* row1 = row0 + 8 * LDO;
#pragma unroll
    for (int f = 0; f < NFRAG; f++) {
        int col = 8 * f + 2 * c;
        float2 v0, v1;
        v0.x = acc[f][0] * dinv0; v0.y = acc[f][1] * dinv0;
        v1.x = acc[f][2] * dinv1; v1.y = acc[f][3] * dinv1;
        if (DO_ELU) {
            v0.x = elu1(v0.x); v0.y = elu1(v0.y);
            v1.x = elu1(v1.x); v1.y = elu1(v1.y);
        }
        *(float2*)&row0[col] = v0;
        *(float2*)&row1[col] = v1;
    }
}

// ---------------- batched tiled SGEMM: C[b] = A @ B[b] ----------------
__global__ __launch_bounds__(256) void gemm_kernel(
    const float* __restrict__ A, const float* __restrict__ B, float* __restrict__ C,
    int M, int N, int K)
{
    __shared__ float Asm[16][132];
    __shared__ float Bsm[16][64];
    int tid = threadIdx.x;
    int bz  = blockIdx.z;
    B += (size_t)bz * K * N;
    C += (size_t)bz * M * N;
    int i0 = blockIdx.x * 128;
    int n0 = blockIdx.y * 64;
    int tr = tid >> 3;
    int tc = tid & 7;

    float acc[4][8];
#pragma unroll
    for (int m = 0; m < 4; m++)
#pragma unroll
        for (int n = 0; n < 8; n++) acc[m][n] = 0.f;

    int ar  = tid >> 2;
    int akq = tid & 3;
    int br  = tid >> 4;
    int bq  = tid & 15;

    for (int k0 = 0; k0 < K; k0 += 16) {
#pragma unroll
        for (int h = 0; h < 2; h++) {
            int rr = ar + h * 64;
            float4 v = *(const float4*)&A[(size_t)(i0 + rr) * K + k0 + akq * 4];
            Asm[akq * 4 + 0][rr] = v.x;
            Asm[akq * 4 + 1][rr] = v.y;
            Asm[akq * 4 + 2][rr] = v.z;
            Asm[akq * 4 + 3][rr] = v.w;
        }
        *(float4*)&Bsm[br][bq * 4] =
            *(const float4*)&B[(size_t)(k0 + br) * N + n0 + bq * 4];
        __syncthreads();
#pragma unroll
        for (int k = 0; k < 16; k++) {
            float4 a4 = *(const float4*)&Asm[k][tr * 4];
            float a[4] = {a4.x, a4.y, a4.z, a4.w};
            float b[8];
            *(float4*)&b[0] = *(const float4*)&Bsm[k][tc * 8];
            *(float4*)&b[4] = *(const float4*)&Bsm[k][tc * 8 + 4];
#pragma unroll
            for (int m = 0; m < 4; m++)
#pragma unroll
                for (int n = 0; n < 8; n++)
                    acc[m][n] = fmaf(a[m], b[n], acc[m][n]);
        }
        __syncthreads();
    }
#pragma unroll
    for (int m = 0; m < 4; m++) {
        int rr = i0 + tr * 4 + m;
#pragma unroll
        for (int nq = 0; nq < 2; nq++) {
            float4 v = make_float4(acc[m][nq * 4 + 0], acc[m][nq * 4 + 1],
                                   acc[m][nq * 4 + 2], acc[m][nq * 4 + 3]);
            *(float4*)&C[(size_t)rr * N + n0 + tc * 8 + nq * 4] = v;
        }
    }
}

// ---------------- s1/s2 = Wh @ a1, Wh @ a2 (warp per row) ----------------
__global__ __launch_bounds__(256) void scores_kernel(
    const float* __restrict__ Wh, const float* __restrict__ a1,
    const float* __restrict__ a2, float* __restrict__ s1, float* __restrict__ s2,
    int N, int Dd)
{
    int b = blockIdx.y;
    Wh += (size_t)b * N * Dd;
    a1 += b * Dd; a2 += b * Dd;
    s1 += (size_t)b * N; s2 += (size_t)b * N;
    int warp = threadIdx.x >> 5, lane = threadIdx.x & 31;
    int i = blockIdx.x * 8 + warp;
    const float* row = Wh + (size_t)i * Dd;
    float v1 = 0.f, v2 = 0.f;
    for (int d = lane; d < Dd; d += 32) {
        float w = row[d];
        v1 = fmaf(w, a1[d], v1);
        v2 = fmaf(w, a2[d], v2);
    }
#pragma unroll
    for (int o = 16; o > 0; o >>= 1) {
        v1 += __shfl_xor_sync(~0u, v1, o);
        v2 += __shfl_xor_sync(~0u, v2, o);
    }
    if (lane == 0) { s1[i] = v1; s2[i] = v2; }
}

// ---------------- per-batch max over s2 ----------------
__global__ __launch_bounds__(256) void max_kernel(
    const float* __restrict__ s2, float* __restrict__ out, int N)
{
    int b = blockIdx.x;
    s2 += (size_t)b * N;
    __shared__ float red[256];
    float m = -1e30f;
    for (int i = threadIdx.x; i < N; i += 256) m = fmaxf(m, s2[i]);
    red[threadIdx.x] = m;
    __syncthreads();
    for (int s = 128; s > 0; s >>= 1) {
        if (threadIdx.x < s) red[threadIdx.x] = fmaxf(red[threadIdx.x], red[threadIdx.x + s]);
        __syncthreads();
    }
    if (threadIdx.x == 0) out[b] = red[0];
}

// ---------------- elu + log_softmax over 256 cols (warp per row) ----------------
__global__ __launch_bounds__(256) void final_kernel(
    const float* __restrict__ in, float* __restrict__ out)
{
    int warp = threadIdx.x >> 5, lane = threadIdx.x & 31;
    int row = blockIdx.x * 8 + warp;
    const float* r = in + (size_t)row * FOUT;
    float v[8];
    float mx = -1e30f;
#pragma unroll
    for (int k = 0; k < 8; k++) {
        float x = r[lane + k * 32];
        x = elu1(x);
        v[k] = x;
        mx = fmaxf(mx, x);
    }
#pragma unroll
    for (int o = 16; o > 0; o >>= 1) mx = fmaxf(mx, __shfl_xor_sync(~0u, mx, o));
    float s = 0.f;
#pragma unroll
    for (int k = 0; k < 8; k++) s += fast_exp(v[k] - mx);
#pragma unroll
    for (int o = 16; o > 0; o >>= 1) s += __shfl_xor_sync(~0u, s, o);
    float lse = mx + logf(s);
#pragma unroll
    for (int k = 0; k < 8; k++) out[(size_t)row * FOUT + lane + k * 32] = v[k] - lse;
}

// ---------------- launcher ----------------
extern "C" void kernel_launch(void* const* d_in, const int* in_sizes, int n_in,
                              void* d_out, int out_size)
{
    const float* x        = (const float*)d_in[0];
    const int*   adj      = (const int*)  d_in[1];
    const float* W_heads  = (const float*)d_in[2];
    const float* a1_heads = (const float*)d_in[3];
    const float* a2_heads = (const float*)d_in[4];
    const float* W_out    = (const float*)d_in[5];
    const float* a1_out   = (const float*)d_in[6];
    const float* a2_out   = (const float*)d_in[7];
    float* out = (float*)d_out;

    float *Wh1, *hbuf, *Wh2, *out2, *s1, *s2, *s2m, *s1b, *s2b, *s2mb;
    uint32_t* adjb;
    cudaGetSymbolAddress((void**)&Wh1,  g_Wh1);
    cudaGetSymbolAddress((void**)&hbuf, g_h);
    cudaGetSymbolAddress((void**)&Wh2,  g_Wh2);
    cudaGetSymbolAddress((void**)&out2, g_out2);
    cudaGetSymbolAddress((void**)&adjb, g_adjbits);
    cudaGetSymbolAddress((void**)&s1,   g_s1);
    cudaGetSymbolAddress((void**)&s2,   g_s2);
    cudaGetSymbolAddress((void**)&s2m,  g_s2m);
    cudaGetSymbolAddress((void**)&s1b,  g_s1b);
    cudaGetSymbolAddress((void**)&s2b,  g_s2b);
    cudaGetSymbolAddress((void**)&s2mb, g_s2mb);

    // ---- shared prep ----
    pack_adj<<<(N_NODES * (N_NODES / 32)) / 256, 256>>>(adj, adjb);

    // ---- layer 1 ----
    gemm_kernel<<<dim3(N_NODES / 128, 1, HEADS), 256>>>(x, W_heads, Wh1, N_NODES, HID, FIN);
    scores_kernel<<<dim3(N_NODES / 8, HEADS), 256>>>(Wh1, a1_heads, a2_heads, s1, s2, N_NODES, HID);
    max_kernel<<<HEADS, 256>>>(s2, s2m, N_NODES);
    attn_mma<HID, 64, HEADS * HID, 1><<<dim3(N_NODES / 128, 1, HEADS), 256>>>(
        Wh1, s1, s2, s2m, adjb, hbuf);

    // ---- layer 2 ----
    gemm_kernel<<<dim3(N_NODES / 128, FOUT / 64, 1), 256>>>(hbuf, W_out, Wh2, N_NODES, FOUT, FIN);
    scores_kernel<<<dim3(N_NODES / 8, 1), 256>>>(Wh2, a1_out, a2_out, s1b, s2b, N_NODES, FOUT);
    max_kernel<<<1, 256>>>(s2b, s2mb, N_NODES);
    attn_mma<FOUT, 128, FOUT, 0><<<dim3(N_NODES / 128, 2, 1), 256>>>(
        Wh2, s1b, s2b, s2mb, adjb, out2);

    // ---- elu + log_softmax ----
    final_kernel<<<N_NODES / 8, 256>>>(out2, out);
}

// round 5
// speedup vs baseline: 1.7851x; 1.0029x over previous
#include <cuda_runtime.h>
#include <cstdint>

// ---------------- problem constants ----------------
#define N_NODES 4096
#define FIN     512
#define HID     64
#define HEADS   8
#define FOUT    256

// ---------------- scratch (device globals; no allocation allowed) ----------------
__device__ float    g_Wh1[(size_t)HEADS * N_NODES * HID];       // 8 MB fp32
__device__ uint32_t g_Vb1[(size_t)HEADS * (N_NODES / 2) * HID]; // 4 MB bf16 pairs
__device__ float    g_h[(size_t)N_NODES * (HEADS * HID)];       // 8 MB fp32
__device__ float    g_Wh2[(size_t)N_NODES * FOUT];              // 4 MB fp32
__device__ uint32_t g_Vb2[(size_t)(N_NODES / 2) * FOUT];        // 2 MB bf16 pairs
__device__ float    g_out2[(size_t)N_NODES * FOUT];             // 4 MB
__device__ uint32_t g_adjbits[(size_t)N_NODES * (N_NODES / 32)];// 2 MB bitmask
__device__ float    g_s1[HEADS * N_NODES];
__device__ float    g_s2[HEADS * N_NODES];
__device__ float    g_s2m[HEADS];
__device__ float    g_s1b[N_NODES];
__device__ float    g_s2b[N_NODES];
__device__ float    g_s2mb[1];

// ---------------- small PTX helpers ----------------
__device__ __forceinline__ uint32_t smem_u32(const void* p) {
    uint32_t a;
    asm("{ .reg .u64 t; cvta.to.shared.u64 t, %1; cvt.u32.u64 %0, t; }" : "=r"(a) : "l"(p));
    return a;
}
#define CP_ASYNC16(dst, src) \
    asm volatile("cp.async.cg.shared.global [%0], [%1], 16;" :: "r"(dst), "l"(src) : "memory")
#define CP_COMMIT() asm volatile("cp.async.commit_group;" ::: "memory")
#define CP_WAIT(n)  asm volatile("cp.async.wait_group %0;" :: "n"(n) : "memory")

// pack two floats -> bf16x2 {lo, hi} (first arg = low half)
__device__ __forceinline__ uint32_t packbf(float lo, float hi) {
    uint32_t r;
    asm("cvt.rn.bf16x2.f32 %0, %1, %2;" : "=r"(r) : "f"(hi), "f"(lo));
    return r;
}

// mma.sync m16n8k16 bf16 (A row-major regs, B col-major regs), D += A*B
__device__ __forceinline__ void mma_bf16(float* d, const uint32_t* a,
                                         uint32_t b0, uint32_t b1) {
    asm volatile(
        "mma.sync.aligned.m16n8k16.row.col.f32.bf16.bf16.f32 "
        "{%0,%1,%2,%3},{%4,%5,%6,%7},{%8,%9},{%0,%1,%2,%3};"
        : "+f"(d[0]), "+f"(d[1]), "+f"(d[2]), "+f"(d[3])
        : "r"(a[0]), "r"(a[1]), "r"(a[2]), "r"(a[3]), "r"(b0), "r"(b1));
}

// ---------------- fast exp: FMA-pipe only ----------------
__device__ __forceinline__ float fast_exp(float x) {
    float y = x * 1.4426950408889634f;
    float t = y + 12582912.0f;            // 1.5 * 2^23
    int   i = __float_as_int(t);
    float f = y - (t - 12582912.0f);
    float p = 1.5403530e-4f;
    p = fmaf(p, f, 1.3333558e-3f);
    p = fmaf(p, f, 9.6181291e-3f);
    p = fmaf(p, f, 5.5504109e-2f);
    p = fmaf(p, f, 2.4022651e-1f);
    p = fmaf(p, f, 6.9314718e-1f);
    p = fmaf(p, f, 1.0f);
    return __int_as_float(__float_as_int(p) + (i << 23));
}
__device__ __forceinline__ float lrelu02(float t) { return fmaxf(t, 0.2f * t); }
__device__ __forceinline__ float elu1(float x) { return x > 0.f ? x : expm1f(x); }

// ---------------- pack adj into row-major bitmask ----------------
__global__ __launch_bounds__(256) void pack_adj(const int* __restrict__ adj,
                                                uint32_t* __restrict__ bits) {
    int w = blockIdx.x * 256 + threadIdx.x;
    const int4* src = (const int4*)(adj + (size_t)w * 32);
    uint32_t m = 0;
#pragma unroll
    for (int q = 0; q < 8; q++) {
        int4 a = src[q];
        m |= (uint32_t)(a.x > 0) << (q * 4 + 0);
        m |= (uint32_t)(a.y > 0) << (q * 4 + 1);
        m |= (uint32_t)(a.z > 0) << (q * 4 + 2);
        m |= (uint32_t)(a.w > 0) << (q * 4 + 3);
    }
    bits[w] = m;
}

// ---------------- convert fp32 V -> bf16 j-pair-interleaved ----------------
// Vb[jp][n] = {lo = bf16(V[2jp][n]), hi = bf16(V[2jp+1][n])}
__global__ __launch_bounds__(256) void cvtV(const float* __restrict__ Wh,
                                            uint32_t* __restrict__ Vb, int C) {
    int idx = blockIdx.x * 256 + threadIdx.x;    // float4-group index
    int cq = C / 4;
    int jp = idx / cq, q = idx % cq;
    float4 e = *(const float4*)(Wh + (size_t)(2 * jp) * C + 4 * q);
    float4 o = *(const float4*)(Wh + (size_t)(2 * jp + 1) * C + 4 * q);
    uint4 r;
    r.x = packbf(e.x, o.x);
    r.y = packbf(e.y, o.y);
    r.z = packbf(e.z, o.z);
    r.w = packbf(e.w, o.w);
    *(uint4*)(Vb + (size_t)jp * C + 4 * q) = r;
}

// =================== fused attention with bf16 mma.sync P@V ===================
// 256 thr (8 warps). RPB=128: warp w -> rows [16w,16w+16), all NCOLS cols.
// RPB=64: warp w -> rows [16(w&3),+16), col-half (w>>2)*64. Per 64-j tile:
// P computed straight into bf16x2 A-fragments; V tile (bf16 pairs) staged via
// cp.async double-buffered so the load overlaps mma(t)+computeP(t+1).
template<int NCOLS, int RPB, int OUTZ, int LDO, int DO_ELU>
__global__ void __launch_bounds__(256) attn_mma(
    const uint32_t* __restrict__ Vb, int vrstride, int vzstride,
    const float* __restrict__ s1g, const float* __restrict__ s2g,
    const float* __restrict__ s2mg, const uint32_t* __restrict__ adjb,
    float* __restrict__ out)
{
    constexpr int NFRAG = 8;                 // 64 cols per warp
    constexpr int SVP = NCOLS + 8;           // u32 stride, == 8 mod 32
    constexpr int T = N_NODES / 64;

    __shared__ uint32_t vsm[2][32 * SVP];

    int tid = threadIdx.x, wid = tid >> 5, lane = tid & 31;
    int g = lane >> 2, c = lane & 3;
    int z = blockIdx.z;
    const uint32_t* vsrc = Vb + (size_t)z * vzstride + blockIdx.y * NCOLS;
    s1g += (size_t)z * N_NODES;
    s2g += (size_t)z * N_NODES;

    int i0 = blockIdx.x * RPB;
    int rowgrp = (RPB == 128) ? wid : (wid & 3);
    int colofs = (RPB == 128) ? 0 : ((wid >> 2) * 64);
    int r0 = i0 + rowgrp * 16 + g;
    int outc = z * OUTZ + blockIdx.y * NCOLS + colofs;

    float s1a = s1g[r0], s1b = s1g[r0 + 8];
    float s2max = s2mg[z];
    float Ma = lrelu02(s1a + s2max), Mb = lrelu02(s1b + s2max);
    const uint2* adjrow0 = (const uint2*)(adjb + (size_t)r0 * (N_NODES / 32));
    const uint2* adjrow1 = (const uint2*)(adjb + (size_t)(r0 + 8) * (N_NODES / 32));

    float acc[NFRAG][4];
#pragma unroll
    for (int f = 0; f < NFRAG; f++)
#pragma unroll
        for (int q = 0; q < 4; q++) acc[f][q] = 0.f;
    uint32_t aPn[4][4];
    float dacc0 = 0.f, dacc1 = 0.f;

    uint32_t vbase = smem_u32(&vsm[0][0]);

    auto issueV = [&](int t, int bufi) {
        int j0h = t * 32;                    // pair-row base
#pragma unroll
        for (int u = 0; u < (32 * NCOLS / 4) / 256; u++) {
            int idx = tid + 256 * u;
            int jp = idx / (NCOLS / 4);
            int q  = idx % (NCOLS / 4);
            uint32_t dst = vbase + (uint32_t)(bufi * 32 * SVP + jp * SVP + q * 4) * 4;
            const uint32_t* src = vsrc + (size_t)(j0h + jp) * vrstride + q * 4;
            CP_ASYNC16(dst, src);
        }
        CP_COMMIT();
    };

    auto computeP = [&](int j0) {
        uint2 w0 = adjrow0[j0 >> 6];
        uint2 w1 = adjrow1[j0 >> 6];
        unsigned long long bm0 = (unsigned long long)w0.x | ((unsigned long long)w0.y << 32);
        unsigned long long bm1 = (unsigned long long)w1.x | ((unsigned long long)w1.y << 32);
#pragma unroll
        for (int ks = 0; ks < 4; ks++) {
            int base = 16 * ks + 2 * c;
            float2 sA = *(const float2*)(s2g + j0 + base);
            float2 sB = *(const float2*)(s2g + j0 + base + 8);
            float p00 = ((bm0 >> base) & 1ULL)       ? fast_exp(lrelu02(s1a + sA.x) - Ma) : 0.f;
            float p01 = ((bm0 >> (base + 1)) & 1ULL) ? fast_exp(lrelu02(s1a + sA.y) - Ma) : 0.f;
            float p10 = ((bm1 >> base) & 1ULL)       ? fast_exp(lrelu02(s1b + sA.x) - Mb) : 0.f;
            float p11 = ((bm1 >> (base + 1)) & 1ULL) ? fast_exp(lrelu02(s1b + sA.y) - Mb) : 0.f;
            float p02 = ((bm0 >> (base + 8)) & 1ULL) ? fast_exp(lrelu02(s1a + sB.x) - Ma) : 0.f;
            float p03 = ((bm0 >> (base + 9)) & 1ULL) ? fast_exp(lrelu02(s1a + sB.y) - Ma) : 0.f;
            float p12 = ((bm1 >> (base + 8)) & 1ULL) ? fast_exp(lrelu02(s1b + sB.x) - Mb) : 0.f;
            float p13 = ((bm1 >> (base + 9)) & 1ULL) ? fast_exp(lrelu02(s1b + sB.y) - Mb) : 0.f;
            dacc0 += (p00 + p01) + (p02 + p03);
            dacc1 += (p10 + p11) + (p12 + p13);
            aPn[ks][0] = packbf(p00, p01);
            aPn[ks][1] = packbf(p10, p11);
            aPn[ks][2] = packbf(p02, p03);
            aPn[ks][3] = packbf(p12, p13);
        }
    };

    issueV(0, 0);
    computeP(0);

    for (int t = 0; t < T; t++) {
        if (t + 1 < T) { issueV(t + 1, (t + 1) & 1); CP_WAIT(1); }
        else           { CP_WAIT(0); }
        __syncthreads();
        const uint32_t* vb = &vsm[t & 1][0];
#pragma unroll
        for (int f = 0; f < NFRAG; f++) {
            int col = colofs + 8 * f + g;
#pragma unroll
            for (int ks = 0; ks < 4; ks++) {
                uint32_t b0 = vb[(ks * 8 + c) * SVP + col];
                uint32_t b1 = vb[(ks * 8 + c + 4) * SVP + col];
                mma_bf16(acc[f], aPn[ks], b0, b1);
            }
        }
        if (t + 1 < T) computeP((t + 1) * 64);
        __syncthreads();
    }

    // denominator: reduce over 4 lanes sharing a row
    dacc0 += __shfl_xor_sync(~0u, dacc0, 1);
    dacc0 += __shfl_xor_sync(~0u, dacc0, 2);
    dacc1 += __shfl_xor_sync(~0u, dacc1, 1);
    dacc1 += __shfl_xor_sync(~0u, dacc1, 2);
    float dinv0 = 1.0f / dacc0;
    float dinv1 = 1.0f / dacc1;

    float* row0 = out + (size_t)r0 * LDO + outc;
    float* row1 = row0 + 8 * LDO;
#pragma unroll
    for (int f = 0; f < NFRAG; f++) {
        int col = 8 * f + 2 * c;
        float2 v0, v1;
        v0.x = acc[f][0] * dinv0; v0.y = acc[f][1] * dinv0;
        v1.x = acc[f][2] * dinv1; v1.y = acc[f][3] * dinv1;
        if (DO_ELU) {
            v0.x = elu1(v0.x); v0.y = elu1(v0.y);
            v1.x = elu1(v1.x); v1.y = elu1(v1.y);
        }
        *(float2*)&row0[col] = v0;
        *(float2*)&row1[col] = v1;
    }
}

// ---------------- batched tiled SGEMM: C[b] = A @ B[b] ----------------
__global__ __launch_bounds__(256) void gemm_kernel(
    const float* __restrict__ A, const float* __restrict__ B, float* __restrict__ C,
    int M, int N, int K)
{
    __shared__ float Asm[16][132];
    __shared__ float Bsm[16][64];
    int tid = threadIdx.x;
    int bz  = blockIdx.z;
    B += (size_t)bz * K * N;
    C += (size_t)bz * M * N;
    int i0 = blockIdx.x * 128;
    int n0 = blockIdx.y * 64;
    int tr = tid >> 3;
    int tc = tid & 7;

    float acc[4][8];
#pragma unroll
    for (int m = 0; m < 4; m++)
#pragma unroll
        for (int n = 0; n < 8; n++) acc[m][n] = 0.f;

    int ar  = tid >> 2;
    int akq = tid & 3;
    int br  = tid >> 4;
    int bq  = tid & 15;

    for (int k0 = 0; k0 < K; k0 += 16) {
#pragma unroll
        for (int h = 0; h < 2; h++) {
            int rr = ar + h * 64;
            float4 v = *(const float4*)&A[(size_t)(i0 + rr) * K + k0 + akq * 4];
            Asm[akq * 4 + 0][rr] = v.x;
            Asm[akq * 4 + 1][rr] = v.y;
            Asm[akq * 4 + 2][rr] = v.z;
            Asm[akq * 4 + 3][rr] = v.w;
        }
        *(float4*)&Bsm[br][bq * 4] =
            *(const float4*)&B[(size_t)(k0 + br) * N + n0 + bq * 4];
        __syncthreads();
#pragma unroll
        for (int k = 0; k < 16; k++) {
            float4 a4 = *(const float4*)&Asm[k][tr * 4];
            float a[4] = {a4.x, a4.y, a4.z, a4.w};
            float b[8];
            *(float4*)&b[0] = *(const float4*)&Bsm[k][tc * 8];
            *(float4*)&b[4] = *(const float4*)&Bsm[k][tc * 8 + 4];
#pragma unroll
            for (int m = 0; m < 4; m++)
#pragma unroll
                for (int n = 0; n < 8; n++)
                    acc[m][n] = fmaf(a[m], b[n], acc[m][n]);
        }
        __syncthreads();
    }
#pragma unroll
    for (int m = 0; m < 4; m++) {
        int rr = i0 + tr * 4 + m;
#pragma unroll
        for (int nq = 0; nq < 2; nq++) {
            float4 v = make_float4(acc[m][nq * 4 + 0], acc[m][nq * 4 + 1],
                                   acc[m][nq * 4 + 2], acc[m][nq * 4 + 3]);
            *(float4*)&C[(size_t)rr * N + n0 + tc * 8 + nq * 4] = v;
        }
    }
}

// ---------------- s1/s2 = Wh @ a1, Wh @ a2 (warp per row) ----------------
__global__ __launch_bounds__(256) void scores_kernel(
    const float* __restrict__ Wh, const float* __restrict__ a1,
    const float* __restrict__ a2, float* __restrict__ s1, float* __restrict__ s2,
    int N, int Dd)
{
    int b = blockIdx.y;
    Wh += (size_t)b * N * Dd;
    a1 += b * Dd; a2 += b * Dd;
    s1 += (size_t)b * N; s2 += (size_t)b * N;
    int warp = threadIdx.x >> 5, lane = threadIdx.x & 31;
    int i = blockIdx.x * 8 + warp;
    const float* row = Wh + (size_t)i * Dd;
    float v1 = 0.f, v2 = 0.f;
    for (int d = lane; d < Dd; d += 32) {
        float w = row[d];
        v1 = fmaf(w, a1[d], v1);
        v2 = fmaf(w, a2[d], v2);
    }
#pragma unroll
    for (int o = 16; o > 0; o >>= 1) {
        v1 += __shfl_xor_sync(~0u, v1, o);
        v2 += __shfl_xor_sync(~0u, v2, o);
    }
    if (lane == 0) { s1[i] = v1; s2[i] = v2; }
}

// ---------------- per-batch max over s2 ----------------
__global__ __launch_bounds__(256) void max_kernel(
    const float* __restrict__ s2, float* __restrict__ out, int N)
{
    int b = blockIdx.x;
    s2 += (size_t)b * N;
    __shared__ float red[256];
    float m = -1e30f;
    for (int i = threadIdx.x; i < N; i += 256) m = fmaxf(m, s2[i]);
    red[threadIdx.x] = m;
    __syncthreads();
    for (int s = 128; s > 0; s >>= 1) {
        if (threadIdx.x < s) red[threadIdx.x] = fmaxf(red[threadIdx.x], red[threadIdx.x + s]);
        __syncthreads();
    }
    if (threadIdx.x == 0) out[b] = red[0];
}

// ---------------- elu + log_softmax over 256 cols (warp per row) ----------------
__global__ __launch_bounds__(256) void final_kernel(
    const float* __restrict__ in, float* __restrict__ out)
{
    int warp = threadIdx.x >> 5, lane = threadIdx.x & 31;
    int row = blockIdx.x * 8 + warp;
    const float* r = in + (size_t)row * FOUT;
    float v[8];
    float mx = -1e30f;
#pragma unroll
    for (int k = 0; k < 8; k++) {
        float x = r[lane + k * 32];
        x = elu1(x);
        v[k] = x;
        mx = fmaxf(mx, x);
    }
#pragma unroll
    for (int o = 16; o > 0; o >>= 1) mx = fmaxf(mx, __shfl_xor_sync(~0u, mx, o));
    float s = 0.f;
#pragma unroll
    for (int k = 0; k < 8; k++) s += fast_exp(v[k] - mx);
#pragma unroll
    for (int o = 16; o > 0; o >>= 1) s += __shfl_xor_sync(~0u, s, o);
    float lse = mx + logf(s);
#pragma unroll
    for (int k = 0; k < 8; k++) out[(size_t)row * FOUT + lane + k * 32] = v[k] - lse;
}

// ---------------- launcher ----------------
extern "C" void kernel_launch(void* const* d_in, const int* in_sizes, int n_in,
                              void* d_out, int out_size)
{
    const float* x        = (const float*)d_in[0];
    const int*   adj      = (const int*)  d_in[1];
    const float* W_heads  = (const float*)d_in[2];
    const float* a1_heads = (const float*)d_in[3];
    const float* a2_heads = (const float*)d_in[4];
    const float* W_out    = (const float*)d_in[5];
    const float* a1_out   = (const float*)d_in[6];
    const float* a2_out   = (const float*)d_in[7];
    float* out = (float*)d_out;

    float *Wh1, *hbuf, *Wh2, *out2, *s1, *s2, *s2m, *s1b, *s2b, *s2mb;
    uint32_t *adjb, *Vb1, *Vb2;
    cudaGetSymbolAddress((void**)&Wh1,  g_Wh1);
    cudaGetSymbolAddress((void**)&Vb1,  g_Vb1);
    cudaGetSymbolAddress((void**)&hbuf, g_h);
    cudaGetSymbolAddress((void**)&Wh2,  g_Wh2);
    cudaGetSymbolAddress((void**)&Vb2,  g_Vb2);
    cudaGetSymbolAddress((void**)&out2, g_out2);
    cudaGetSymbolAddress((void**)&adjb, g_adjbits);
    cudaGetSymbolAddress((void**)&s1,   g_s1);
    cudaGetSymbolAddress((void**)&s2,   g_s2);
    cudaGetSymbolAddress((void**)&s2m,  g_s2m);
    cudaGetSymbolAddress((void**)&s1b,  g_s1b);
    cudaGetSymbolAddress((void**)&s2b,  g_s2b);
    cudaGetSymbolAddress((void**)&s2mb, g_s2mb);

    // ---- shared prep ----
    pack_adj<<<(N_NODES * (N_NODES / 32)) / 256, 256>>>(adj, adjb);

    // ---- layer 1 ----
    gemm_kernel<<<dim3(N_NODES / 128, 1, HEADS), 256>>>(x, W_heads, Wh1, N_NODES, HID, FIN);
    scores_kernel<<<dim3(N_NODES / 8, HEADS), 256>>>(Wh1, a1_heads, a2_heads, s1, s2, N_NODES, HID);
    max_kernel<<<HEADS, 256>>>(s2, s2m, N_NODES);
    cvtV<<<(HEADS * (N_NODES / 2) * HID / 4) / 256, 256>>>(Wh1, Vb1, HID);
    attn_mma<HID, 128, HID, HEADS * HID, 1><<<dim3(N_NODES / 128, 1, HEADS), 256>>>(
        Vb1, HID, (N_NODES / 2) * HID, s1, s2, s2m, adjb, hbuf);

    // ---- layer 2 ----
    gemm_kernel<<<dim3(N_NODES / 128, FOUT / 64, 1), 256>>>(hbuf, W_out, Wh2, N_NODES, FOUT, FIN);
    scores_kernel<<<dim3(N_NODES / 8, 1), 256>>>(Wh2, a1_out, a2_out, s1b, s2b, N_NODES, FOUT);
    max_kernel<<<1, 256>>>(s2b, s2mb, N_NODES);
    cvtV<<<((N_NODES / 2) * FOUT / 4) / 256, 256>>>(Wh2, Vb2, FOUT);
    attn_mma<128, 64, 0, FOUT, 0><<<dim3(N_NODES / 64, 2, 1), 256>>>(
        Vb2, FOUT, 0, s1b, s2b, s2mb, adjb, out2);

    // ---- elu + log_softmax ----
    final_kernel<<<N_NODES / 8, 256>>>(out2, out);
}

// round 7
// speedup vs baseline: 2.1633x; 1.2119x over previous
#include <cuda_runtime.h>
#include <cstdint>

#define N_NODES 4096
#define FIN     512
#define HID     64
#define HEADS   8
#define FOUT    256

// ---------------- scratch ----------------
__device__ uint32_t g_Vb1[(size_t)HEADS * (N_NODES / 2) * HID]; // bf16 row-pairs
__device__ float    g_h[(size_t)N_NODES * (HEADS * HID)];       // fp32
__device__ uint32_t g_Vb2[(size_t)(N_NODES / 2) * FOUT];        // bf16 row-pairs
__device__ float    g_out2[(size_t)N_NODES * FOUT];
__device__ uint32_t g_adjbits[(size_t)N_NODES * (N_NODES / 32)];
__device__ float    g_s1[HEADS * N_NODES];
__device__ float    g_s2[HEADS * N_NODES];
__device__ float    g_s1b[N_NODES];
__device__ float    g_s2b[N_NODES];
__device__ unsigned g_enc1[HEADS];
__device__ unsigned g_enc2[1];

// ---------------- helpers ----------------
__device__ __forceinline__ uint32_t smem_u32(const void* p) {
    uint32_t a;
    asm("{ .reg .u64 t; cvta.to.shared.u64 t, %1; cvt.u32.u64 %0, t; }" : "=r"(a) : "l"(p));
    return a;
}
#define CP_ASYNC16(dst, src) \
    asm volatile("cp.async.cg.shared.global [%0], [%1], 16;" :: "r"(dst), "l"(src) : "memory")
#define CP_COMMIT() asm volatile("cp.async.commit_group;" ::: "memory")
#define CP_WAIT(n)  asm volatile("cp.async.wait_group %0;" :: "n"(n) : "memory")

__device__ __forceinline__ uint32_t packbf(float lo, float hi) {
    uint32_t r;
    asm("cvt.rn.bf16x2.f32 %0, %1, %2;" : "=r"(r) : "f"(hi), "f"(lo));
    return r;
}
__device__ __forceinline__ void mma_bf16(float* d, const uint32_t* a,
                                         uint32_t b0, uint32_t b1) {
    asm volatile(
        "mma.sync.aligned.m16n8k16.row.col.f32.bf16.bf16.f32 "
        "{%0,%1,%2,%3},{%4,%5,%6,%7},{%8,%9},{%0,%1,%2,%3};"
        : "+f"(d[0]), "+f"(d[1]), "+f"(d[2]), "+f"(d[3])
        : "r"(a[0]), "r"(a[1]), "r"(a[2]), "r"(a[3]), "r"(b0), "r"(b1));
}
__device__ __forceinline__ void mma_tf32(float* d, const float* a, float b0, float b1) {
    asm volatile(
        "mma.sync.aligned.m16n8k8.row.col.f32.tf32.tf32.f32 "
        "{%0,%1,%2,%3},{%4,%5,%6,%7},{%8,%9},{%0,%1,%2,%3};"
        : "+f"(d[0]), "+f"(d[1]), "+f"(d[2]), "+f"(d[3])
        : "r"(__float_as_uint(a[0])), "r"(__float_as_uint(a[1])),
          "r"(__float_as_uint(a[2])), "r"(__float_as_uint(a[3])),
          "r"(__float_as_uint(b0)),   "r"(__float_as_uint(b1)));
}
__device__ __forceinline__ unsigned encf(float f) {
    unsigned u = __float_as_uint(f);
    return (u & 0x80000000u) ? ~u : (u | 0x80000000u);
}
__device__ __forceinline__ float decf(unsigned e) {
    return __uint_as_float((e & 0x80000000u) ? (e & 0x7fffffffu) : ~e);
}
__device__ __forceinline__ float fast_exp(float x) {
    float y = x * 1.4426950408889634f;
    float t = y + 12582912.0f;
    int   i = __float_as_int(t);
    float f = y - (t - 12582912.0f);
    float p = 1.5403530e-4f;
    p = fmaf(p, f, 1.3333558e-3f);
    p = fmaf(p, f, 9.6181291e-3f);
    p = fmaf(p, f, 5.5504109e-2f);
    p = fmaf(p, f, 2.4022651e-1f);
    p = fmaf(p, f, 6.9314718e-1f);
    p = fmaf(p, f, 1.0f);
    return __int_as_float(__float_as_int(p) + (i << 23));
}
__device__ __forceinline__ float lrelu02(float t) { return fmaxf(t, 0.2f * t); }
__device__ __forceinline__ float elu1(float x) { return x > 0.f ? x : expm1f(x); }

// ---------------- tiny kernels ----------------
__global__ __launch_bounds__(256) void zero_misc(float* s1b, float* s2b,
                                                 unsigned* e1, unsigned* e2) {
    int i = blockIdx.x * 256 + threadIdx.x;
    if (i < N_NODES) { s1b[i] = 0.f; s2b[i] = 0.f; }
    if (i < HEADS) e1[i] = 0u;
    if (i == 0) e2[0] = 0u;
}
__global__ __launch_bounds__(256) void pack_adj(const int* __restrict__ adj,
                                                uint32_t* __restrict__ bits) {
    int w = blockIdx.x * 256 + threadIdx.x;
    const int4* src = (const int4*)(adj + (size_t)w * 32);
    uint32_t m = 0;
#pragma unroll
    for (int q = 0; q < 8; q++) {
        int4 a = src[q];
        m |= (uint32_t)(a.x > 0) << (q * 4 + 0);
        m |= (uint32_t)(a.y > 0) << (q * 4 + 1);
        m |= (uint32_t)(a.z > 0) << (q * 4 + 2);
        m |= (uint32_t)(a.w > 0) << (q * 4 + 3);
    }
    bits[w] = m;
}
__global__ __launch_bounds__(256) void max2_kernel(const float* __restrict__ s2,
                                                   unsigned* __restrict__ enc) {
    __shared__ float red[256];
    float m = -1e30f;
    for (int i = threadIdx.x; i < N_NODES; i += 256) m = fmaxf(m, s2[i]);
    red[threadIdx.x] = m;
    __syncthreads();
    for (int s = 128; s > 0; s >>= 1) {
        if (threadIdx.x < s) red[threadIdx.x] = fmaxf(red[threadIdx.x], red[threadIdx.x + s]);
        __syncthreads();
    }
    if (threadIdx.x == 0) enc[0] = encf(red[0]);
}

// ------------- tf32 tensor GEMM, fused epilogue -------------
// C = A[M,512] @ B[512,NB] (per z). Output: Vb bf16 row-pair-interleaved
// [M/2][NB] u32, s1/s2 = C@a1 / C@a2 (L1: direct store + atomicMax enc of s2;
// else atomicAdd partials over col-blocks). BM=128, BN=64, BK=16, 256 threads.
template<int L1>
__global__ void __launch_bounds__(256) gemm_tc(
    const float* __restrict__ A, const float* __restrict__ B,
    uint32_t* __restrict__ Vb, const float* __restrict__ a1,
    const float* __restrict__ a2, float* __restrict__ s1, float* __restrict__ s2,
    unsigned* __restrict__ enc, int NB, int bB, int bV, int bA, int bS)
{
    constexpr int SA = 20, SB = 72;
    __shared__ float Asm[2][128 * SA];
    __shared__ float Bsm[2][16 * SB];
    __shared__ float a1sm[64], a2sm[64];
    int tid = threadIdx.x, wid = tid >> 5, lane = tid & 31;
    int g = lane >> 2, c = lane & 3;
    int z = blockIdx.z, n0 = blockIdx.y * 64, i0 = blockIdx.x * 128;
    B  += (size_t)z * bB;
    Vb += (size_t)z * bV;
    a1 += (size_t)z * bA;  a2 += (size_t)z * bA;
    s1 += (size_t)z * bS;  s2 += (size_t)z * bS;
    if (tid < 64) { a1sm[tid] = a1[n0 + tid]; a2sm[tid] = a2[n0 + tid]; }
    uint32_t abase = smem_u32(Asm), bbase = smem_u32(Bsm);

    auto issue = [&](int t, int buf) {
        int k0 = t * 16;
#pragma unroll
        for (int u = 0; u < 2; u++) {
            int idx = tid + 256 * u;
            int r = idx >> 2, q = idx & 3;
            CP_ASYNC16(abase + (uint32_t)(buf * 128 * SA + r * SA + q * 4) * 4,
                       A + (size_t)(i0 + r) * FIN + k0 + q * 4);
        }
        {
            int r = tid >> 4, q = tid & 15;
            CP_ASYNC16(bbase + (uint32_t)(buf * 16 * SB + r * SB + q * 4) * 4,
                       B + (size_t)(k0 + r) * NB + n0 + q * 4);
        }
        CP_COMMIT();
    };

    float acc[8][4] = {};
    issue(0, 0);
    for (int t = 0; t < 32; t++) {
        if (t + 1 < 32) { issue(t + 1, (t + 1) & 1); CP_WAIT(1); }
        else            { CP_WAIT(0); }
        __syncthreads();
        const float* As = &Asm[t & 1][0];
        const float* Bs = &Bsm[t & 1][0];
#pragma unroll
        for (int ks = 0; ks < 2; ks++) {
            int k8 = ks * 8;
            float af[4];
            af[0] = As[(16 * wid + g) * SA + k8 + c];
            af[1] = As[(16 * wid + 8 + g) * SA + k8 + c];
            af[2] = As[(16 * wid + g) * SA + k8 + c + 4];
            af[3] = As[(16 * wid + 8 + g) * SA + k8 + c + 4];
#pragma unroll
            for (int f = 0; f < 8; f++) {
                float b0 = Bs[(k8 + c) * SB + 8 * f + g];
                float b1 = Bs[(k8 + c + 4) * SB + 8 * f + g];
                mma_tf32(acc[f], af, b0, b1);
            }
        }
        __syncthreads();
    }

    // ---- epilogue: bf16 row-pair V via shfl pairing ----
    int rA = i0 + 16 * wid + g, rB = rA + 8;
#pragma unroll
    for (int f = 0; f < 8; f++) {
        float p0 = __shfl_xor_sync(~0u, acc[f][0], 4);
        float p1 = __shfl_xor_sync(~0u, acc[f][1], 4);
        float p2 = __shfl_xor_sync(~0u, acc[f][2], 4);
        float p3 = __shfl_xor_sync(~0u, acc[f][3], 4);
        if (!(g & 1)) {
            int col = n0 + 8 * f + 2 * c;
            uint2 v0; v0.x = packbf(acc[f][0], p0); v0.y = packbf(acc[f][1], p1);
            *(uint2*)&Vb[(size_t)(rA >> 1) * NB + col] = v0;
            uint2 v1; v1.x = packbf(acc[f][2], p2); v1.y = packbf(acc[f][3], p3);
            *(uint2*)&Vb[(size_t)(rB >> 1) * NB + col] = v1;
        }
    }
    // ---- epilogue: s1/s2 (exact fp32 from accumulators) ----
    float u1 = 0.f, u2 = 0.f, w1 = 0.f, w2 = 0.f;
#pragma unroll
    for (int f = 0; f < 8; f++) {
        int col = 8 * f + 2 * c;
        u1 += acc[f][0] * a1sm[col] + acc[f][1] * a1sm[col + 1];
        u2 += acc[f][0] * a2sm[col] + acc[f][1] * a2sm[col + 1];
        w1 += acc[f][2] * a1sm[col] + acc[f][3] * a1sm[col + 1];
        w2 += acc[f][2] * a2sm[col] + acc[f][3] * a2sm[col + 1];
    }
    u1 += __shfl_xor_sync(~0u, u1, 1); u1 += __shfl_xor_sync(~0u, u1, 2);
    u2 += __shfl_xor_sync(~0u, u2, 1); u2 += __shfl_xor_sync(~0u, u2, 2);
    w1 += __shfl_xor_sync(~0u, w1, 1); w1 += __shfl_xor_sync(~0u, w1, 2);
    w2 += __shfl_xor_sync(~0u, w2, 1); w2 += __shfl_xor_sync(~0u, w2, 2);
    if (c == 0) {
        if (L1) {
            s1[rA] = u1; s2[rA] = u2; s1[rB] = w1; s2[rB] = w2;
            atomicMax(&enc[z], encf(u2));
            atomicMax(&enc[z], encf(w2));
        } else {
            atomicAdd(&s1[rA], u1); atomicAdd(&s2[rA], u2);
            atomicAdd(&s1[rB], w1); atomicAdd(&s2[rB], w2);
        }
    }
}

// =================== fused attention with bf16 mma.sync P@V ===================
template<int NCOLS, int RPB, int OUTZ, int LDO, int DO_ELU>
__global__ void __launch_bounds__(256) attn_mma(
    const uint32_t* __restrict__ Vb, int vrstride, int vzstride,
    const float* __restrict__ s1g, const float* __restrict__ s2g,
    const unsigned* __restrict__ s2enc, const uint32_t* __restrict__ adjb,
    float* __restrict__ out)
{
    constexpr int NFRAG = 8;
    constexpr int SVP = NCOLS + 8;
    constexpr int T = N_NODES / 64;

    __shared__ uint32_t vsm[2][32 * SVP];

    int tid = threadIdx.x, wid = tid >> 5, lane = tid & 31;
    int g = lane >> 2, c = lane & 3;
    int z = blockIdx.z;
    const uint32_t* vsrc = Vb + (size_t)z * vzstride + blockIdx.y * NCOLS;
    s1g += (size_t)z * N_NODES;
    s2g += (size_t)z * N_NODES;

    int i0 = blockIdx.x * RPB;
    int rowgrp = (RPB == 128) ? wid : (wid & 3);
    int colofs = (RPB == 128) ? 0 : ((wid >> 2) * 64);
    int r0 = i0 + rowgrp * 16 + g;
    int outc = z * OUTZ + blockIdx.y * NCOLS + colofs;

    float s1a = s1g[r0], s1b = s1g[r0 + 8];
    float s2max = decf(s2enc[z]);
    float Ma = lrelu02(s1a + s2max), Mb = lrelu02(s1b + s2max);
    const uint2* adjrow0 = (const uint2*)(adjb + (size_t)r0 * (N_NODES / 32));
    const uint2* adjrow1 = (const uint2*)(adjb + (size_t)(r0 + 8) * (N_NODES / 32));

    float acc[NFRAG][4];
#pragma unroll
    for (int f = 0; f < NFRAG; f++)
#pragma unroll
        for (int q = 0; q < 4; q++) acc[f][q] = 0.f;
    uint32_t aPn[4][4];
    float dacc0 = 0.f, dacc1 = 0.f;
    uint32_t vbase = smem_u32(&vsm[0][0]);

    auto issueV = [&](int t, int bufi) {
        int j0h = t * 32;
#pragma unroll
        for (int u = 0; u < (32 * NCOLS / 4) / 256; u++) {
            int idx = tid + 256 * u;
            int jp = idx / (NCOLS / 4);
            int q  = idx % (NCOLS / 4);
            uint32_t dst = vbase + (uint32_t)(bufi * 32 * SVP + jp * SVP + q * 4) * 4;
            CP_ASYNC16(dst, vsrc + (size_t)(j0h + jp) * vrstride + q * 4);
        }
        CP_COMMIT();
    };
    auto computeP = [&](int j0) {
        uint2 w0 = adjrow0[j0 >> 6];
        uint2 w1 = adjrow1[j0 >> 6];
        unsigned long long bm0 = (unsigned long long)w0.x | ((unsigned long long)w0.y << 32);
        unsigned long long bm1 = (unsigned long long)w1.x | ((unsigned long long)w1.y << 32);
#pragma unroll
        for (int ks = 0; ks < 4; ks++) {
            int base = 16 * ks + 2 * c;
            float2 sA = *(const float2*)(s2g + j0 + base);
            float2 sB = *(const float2*)(s2g + j0 + base + 8);
            float p00 = ((bm0 >> base) & 1ULL)       ? fast_exp(lrelu02(s1a + sA.x) - Ma) : 0.f;
            float p01 = ((bm0 >> (base + 1)) & 1ULL) ? fast_exp(lrelu02(s1a + sA.y) - Ma) : 0.f;
            float p10 = ((bm1 >> base) & 1ULL)       ? fast_exp(lrelu02(s1b + sA.x) - Mb) : 0.f;
            float p11 = ((bm1 >> (base + 1)) & 1ULL) ? fast_exp(lrelu02(s1b + sA.y) - Mb) : 0.f;
            float p02 = ((bm0 >> (base + 8)) & 1ULL) ? fast_exp(lrelu02(s1a + sB.x) - Ma) : 0.f;
            float p03 = ((bm0 >> (base + 9)) & 1ULL) ? fast_exp(lrelu02(s1a + sB.y) - Ma) : 0.f;
            float p12 = ((bm1 >> (base + 8)) & 1ULL) ? fast_exp(lrelu02(s1b + sB.x) - Mb) : 0.f;
            float p13 = ((bm1 >> (base + 9)) & 1ULL) ? fast_exp(lrelu02(s1b + sB.y) - Mb) : 0.f;
            dacc0 += (p00 + p01) + (p02 + p03);
            dacc1 += (p10 + p11) + (p12 + p13);
            aPn[ks][0] = packbf(p00, p01);
            aPn[ks][1] = packbf(p10, p11);
            aPn[ks][2] = packbf(p02, p03);
            aPn[ks][3] = packbf(p12, p13);
        }
    };

    issueV(0, 0);
    computeP(0);
    for (int t = 0; t < T; t++) {
        if (t + 1 < T) { issueV(t + 1, (t + 1) & 1); CP_WAIT(1); }
        else           { CP_WAIT(0); }
        __syncthreads();
        const uint32_t* vb = &vsm[t & 1][0];
#pragma unroll
        for (int f = 0; f < NFRAG; f++) {
            int col = colofs + 8 * f + g;
#pragma unroll
            for (int ks = 0; ks < 4; ks++) {
                uint32_t b0 = vb[(ks * 8 + c) * SVP + col];
                uint32_t b1 = vb[(ks * 8 + c + 4) * SVP + col];
                mma_bf16(acc[f], aPn[ks], b0, b1);
            }
        }
        if (t + 1 < T) computeP((t + 1) * 64);
        __syncthreads();
    }

    dacc0 += __shfl_xor_sync(~0u, dacc0, 1);
    dacc0 += __shfl_xor_sync(~0u, dacc0, 2);
    dacc1 += __shfl_xor_sync(~0u, dacc1, 1);
    dacc1 += __shfl_xor_sync(~0u, dacc1, 2);
    float dinv0 = 1.0f / dacc0;
    float dinv1 = 1.0f / dacc1;

    float* row0 = out + (size_t)r0 * LDO + outc;
    float* row1 = row0 + 8 * LDO;
#pragma unroll
    for (int f = 0; f < NFRAG; f++) {
        int col = 8 * f + 2 * c;
        float2 v0, v1;
        v0.x = acc[f][0] * dinv0; v0.y = acc[f][1] * dinv0;
        v1.x = acc[f][2] * dinv1; v1.y = acc[f][3] * dinv1;
        if (DO_ELU) {
            v0.x = elu1(v0.x); v0.y = elu1(v0.y);
            v1.x = elu1(v1.x); v1.y = elu1(v1.y);
        }
        *(float2*)&row0[col] = v0;
        *(float2*)&row1[col] = v1;
    }
}

// ---------------- elu + log_softmax ----------------
__global__ __launch_bounds__(256) void final_kernel(
    const float* __restrict__ in, float* __restrict__ out)
{
    int warp = threadIdx.x >> 5, lane = threadIdx.x & 31;
    int row = blockIdx.x * 8 + warp;
    const float* r = in + (size_t)row * FOUT;
    float v[8];
    float mx = -1e30f;
#pragma unroll
    for (int k = 0; k < 8; k++) {
        float x = r[lane + k * 32];
        x = elu1(x);
        v[k] = x;
        mx = fmaxf(mx, x);
    }
#pragma unroll
    for (int o = 16; o > 0; o >>= 1) mx = fmaxf(mx, __shfl_xor_sync(~0u, mx, o));
    float s = 0.f;
#pragma unroll
    for (int k = 0; k < 8; k++) s += fast_exp(v[k] - mx);
#pragma unroll
    for (int o = 16; o > 0; o >>= 1) s += __shfl_xor_sync(~0u, s, o);
    float lse = mx + logf(s);
#pragma unroll
    for (int k = 0; k < 8; k++) out[(size_t)row * FOUT + lane + k * 32] = v[k] - lse;
}

// ---------------- launcher ----------------
extern "C" void kernel_launch(void* const* d_in, const int* in_sizes, int n_in,
                              void* d_out, int out_size)
{
    const float* x        = (const float*)d_in[0];
    const int*   adj      = (const int*)  d_in[1];
    const float* W_heads  = (const float*)d_in[2];
    const float* a1_heads = (const float*)d_in[3];
    const float* a2_heads = (const float*)d_in[4];
    const float* W_out    = (const float*)d_in[5];
    const float* a1_out   = (const float*)d_in[6];
    const float* a2_out   = (const float*)d_in[7];
    float* out = (float*)d_out;

    float *hbuf, *out2, *s1, *s2, *s1b, *s2b;
    uint32_t *adjb, *Vb1, *Vb2;
    unsigned *enc1, *enc2;
    cudaGetSymbolAddress((void**)&Vb1,  g_Vb1);
    cudaGetSymbolAddress((void**)&hbuf, g_h);
    cudaGetSymbolAddress((void**)&Vb2,  g_Vb2);
    cudaGetSymbolAddress((void**)&out2, g_out2);
    cudaGetSymbolAddress((void**)&adjb, g_adjbits);
    cudaGetSymbolAddress((void**)&s1,   g_s1);
    cudaGetSymbolAddress((void**)&s2,   g_s2);
    cudaGetSymbolAddress((void**)&s1b,  g_s1b);
    cudaGetSymbolAddress((void**)&s2b,  g_s2b);
    cudaGetSymbolAddress((void**)&enc1, g_enc1);
    cudaGetSymbolAddress((void**)&enc2, g_enc2);

    // 0: zero atomics
    zero_misc<<<16, 256>>>(s1b, s2b, enc1, enc2);
    // 1: adj bitmask
    pack_adj<<<(N_NODES * (N_NODES / 32)) / 256, 256>>>(adj, adjb);
    // 2: layer-1 GEMM (+V bf16 pairs, s1/s2, s2max)
    gemm_tc<1><<<dim3(N_NODES / 128, 1, HEADS), 256>>>(
        x, W_heads, Vb1, a1_heads, a2_heads, s1, s2, enc1,
        HID, FIN * HID, (N_NODES / 2) * HID, HID, N_NODES);
    // 3: layer-1 attention  (<- ncu profiled slot)
    attn_mma<HID, 128, HID, HEADS * HID, 1><<<dim3(N_NODES / 128, 1, HEADS), 256>>>(
        Vb1, HID, (N_NODES / 2) * HID, s1, s2, enc1, adjb, hbuf);
    // 4: layer-2 GEMM (+V bf16 pairs, s1/s2 partials)
    gemm_tc<0><<<dim3(N_NODES / 128, FOUT / 64, 1), 256>>>(
        hbuf, W_out, Vb2, a1_out, a2_out, s1b, s2b, enc2,
        FOUT, 0, 0, 0, 0);
    // 5: layer-2 s2 max
    max2_kernel<<<1, 256>>>(s2b, enc2);
    // 6: layer-2 attention
    attn_mma<128, 64, 0, FOUT, 0><<<dim3(N_NODES / 64, 2, 1), 256>>>(
        Vb2, FOUT, 0, s1b, s2b, enc2, adjb, out2);
    // 7: elu + log_softmax
    final_kernel<<<N_NODES / 8, 256>>>(out2, out);
}

// round 8
// speedup vs baseline: 4.3566x; 2.0139x over previous
#include <cuda_runtime.h>
#include <cstdint>

#define N_NODES 4096
#define FIN     512
#define HID     64
#define HEADS   8
#define FOUT    256

// ---------------- scratch ----------------
__device__ uint32_t g_Vb1[(size_t)HEADS * (N_NODES / 2) * HID]; // bf16 row-pairs
__device__ float    g_h[(size_t)N_NODES * (HEADS * HID)];       // fp32
__device__ uint32_t g_Vb2[(size_t)(N_NODES / 2) * FOUT];        // bf16 row-pairs
__device__ float    g_num[(size_t)2 * N_NODES * FOUT];          // jsplit partials
__device__ float    g_den[2 * N_NODES];
__device__ uint32_t g_adjbits[(size_t)N_NODES * (N_NODES / 32)];
__device__ float    g_s1[HEADS * N_NODES];
__device__ float    g_s2[HEADS * N_NODES];
__device__ float    g_s1b[N_NODES];
__device__ float    g_s2b[N_NODES];
__device__ unsigned g_enc1[HEADS];
__device__ float    g_Ea1[HEADS * N_NODES], g_Eb1[HEADS * N_NODES];
__device__ uint32_t g_F1[HEADS * N_NODES];
__device__ float    g_Ea2[N_NODES], g_Eb2[N_NODES];
__device__ uint32_t g_F2[N_NODES];

// ---------------- helpers ----------------
__device__ __forceinline__ uint32_t smem_u32(const void* p) {
    uint32_t a;
    asm("{ .reg .u64 t; cvta.to.shared.u64 t, %1; cvt.u32.u64 %0, t; }" : "=r"(a) : "l"(p));
    return a;
}
#define CP_ASYNC16(dst, src) \
    asm volatile("cp.async.cg.shared.global [%0], [%1], 16;" :: "r"(dst), "l"(src) : "memory")
#define CP_COMMIT() asm volatile("cp.async.commit_group;" ::: "memory")
#define CP_WAIT(n)  asm volatile("cp.async.wait_group %0;" :: "n"(n) : "memory")

__device__ __forceinline__ uint32_t packbf(float lo, float hi) {
    uint32_t r;
    asm("cvt.rn.bf16x2.f32 %0, %1, %2;" : "=r"(r) : "f"(hi), "f"(lo));
    return r;
}
__device__ __forceinline__ void mma_bf16(float* d, const uint32_t* a,
                                         uint32_t b0, uint32_t b1) {
    asm volatile(
        "mma.sync.aligned.m16n8k16.row.col.f32.bf16.bf16.f32 "
        "{%0,%1,%2,%3},{%4,%5,%6,%7},{%8,%9},{%0,%1,%2,%3};"
        : "+f"(d[0]), "+f"(d[1]), "+f"(d[2]), "+f"(d[3])
        : "r"(a[0]), "r"(a[1]), "r"(a[2]), "r"(a[3]), "r"(b0), "r"(b1));
}
__device__ __forceinline__ void mma_tf32(float* d, const float* a, float b0, float b1) {
    asm volatile(
        "mma.sync.aligned.m16n8k8.row.col.f32.tf32.tf32.f32 "
        "{%0,%1,%2,%3},{%4,%5,%6,%7},{%8,%9},{%0,%1,%2,%3};"
        : "+f"(d[0]), "+f"(d[1]), "+f"(d[2]), "+f"(d[3])
        : "r"(__float_as_uint(a[0])), "r"(__float_as_uint(a[1])),
          "r"(__float_as_uint(a[2])), "r"(__float_as_uint(a[3])),
          "r"(__float_as_uint(b0)),   "r"(__float_as_uint(b1)));
}
__device__ __forceinline__ unsigned encf(float f) {
    unsigned u = __float_as_uint(f);
    return (u & 0x80000000u) ? ~u : (u | 0x80000000u);
}
__device__ __forceinline__ float decf(unsigned e) {
    return __uint_as_float((e & 0x80000000u) ? (e & 0x7fffffffu) : ~e);
}
__device__ __forceinline__ float fast_exp(float x) {
    float y = x * 1.4426950408889634f;
    float t = y + 12582912.0f;
    int   i = __float_as_int(t);
    float f = y - (t - 12582912.0f);
    float p = 1.5403530e-4f;
    p = fmaf(p, f, 1.3333558e-3f);
    p = fmaf(p, f, 9.6181291e-3f);
    p = fmaf(p, f, 5.5504109e-2f);
    p = fmaf(p, f, 2.4022651e-1f);
    p = fmaf(p, f, 6.9314718e-1f);
    p = fmaf(p, f, 1.0f);
    return __int_as_float(__float_as_int(p) + (i << 23));
}
__device__ __forceinline__ float lrelu02(float t) { return fmaxf(t, 0.2f * t); }
__device__ __forceinline__ float elu1(float x) { return x > 0.f ? x : expm1f(x); }

// ---------------- pack adj bitmask + zero atomics ----------------
__global__ __launch_bounds__(256) void pack_adj(const int* __restrict__ adj,
                                                uint32_t* __restrict__ bits,
                                                float* s1b, float* s2b,
                                                unsigned* e1) {
    int w = blockIdx.x * 256 + threadIdx.x;
    const int4* src = (const int4*)(adj + (size_t)w * 32);
    uint32_t m = 0;
#pragma unroll
    for (int q = 0; q < 8; q++) {
        int4 a = src[q];
        m |= (uint32_t)(a.x > 0) << (q * 4 + 0);
        m |= (uint32_t)(a.y > 0) << (q * 4 + 1);
        m |= (uint32_t)(a.z > 0) << (q * 4 + 2);
        m |= (uint32_t)(a.w > 0) << (q * 4 + 3);
    }
    bits[w] = m;
    if (blockIdx.x < 16) {
        int i = blockIdx.x * 256 + threadIdx.x;
        s1b[i] = 0.f; s2b[i] = 0.f;
    }
    if (blockIdx.x == 16 && threadIdx.x < HEADS) e1[threadIdx.x] = 0u;
}

// ---------------- layer-1 factor tables ----------------
__global__ __launch_bounds__(256) void prep1(
    const float* __restrict__ s1, const float* __restrict__ s2,
    const unsigned* __restrict__ enc, float* __restrict__ Ea,
    float* __restrict__ Eb, uint32_t* __restrict__ Ft)
{
    int i = blockIdx.x * 256 + threadIdx.x;
    int z = i >> 12;
    float m2 = decf(enc[z]);
    float v1 = s1[i], v2 = s2[i];
    float M = lrelu02(v1 + m2);
    Ea[i] = fast_exp(v1 - M);
    Eb[i] = fast_exp(0.2f * v1 - M);
    Ft[i] = packbf(fast_exp(v2), fast_exp(0.2f * v2));
}

// ---------------- layer-2: s2 max + factor tables (1 block) ----------------
__global__ __launch_bounds__(256) void max2_prep2(
    const float* __restrict__ s1, const float* __restrict__ s2,
    float* __restrict__ Ea, float* __restrict__ Eb, uint32_t* __restrict__ Ft)
{
    __shared__ float red[256];
    float m = -1e30f;
    for (int i = threadIdx.x; i < N_NODES; i += 256) m = fmaxf(m, s2[i]);
    red[threadIdx.x] = m;
    __syncthreads();
    for (int s = 128; s > 0; s >>= 1) {
        if (threadIdx.x < s) red[threadIdx.x] = fmaxf(red[threadIdx.x], red[threadIdx.x + s]);
        __syncthreads();
    }
    float m2 = red[0];
    for (int r = threadIdx.x; r < N_NODES; r += 256) {
        float v1 = s1[r], v2 = s2[r];
        float M = lrelu02(v1 + m2);
        Ea[r] = fast_exp(v1 - M);
        Eb[r] = fast_exp(0.2f * v1 - M);
        Ft[r] = packbf(fast_exp(v2), fast_exp(0.2f * v2));
    }
}

// ------------- tf32 tensor GEMM, fused epilogue (unchanged from R7) -------------
template<int L1>
__global__ void __launch_bounds__(256) gemm_tc(
    const float* __restrict__ A, const float* __restrict__ B,
    uint32_t* __restrict__ Vb, const float* __restrict__ a1,
    const float* __restrict__ a2, float* __restrict__ s1, float* __restrict__ s2,
    unsigned* __restrict__ enc, int NB, int bB, int bV, int bA, int bS)
{
    constexpr int SA = 20, SB = 72;
    __shared__ float Asm[2][128 * SA];
    __shared__ float Bsm[2][16 * SB];
    __shared__ float a1sm[64], a2sm[64];
    int tid = threadIdx.x, wid = tid >> 5, lane = tid & 31;
    int g = lane >> 2, c = lane & 3;
    int z = blockIdx.z, n0 = blockIdx.y * 64, i0 = blockIdx.x * 128;
    B  += (size_t)z * bB;
    Vb += (size_t)z * bV;
    a1 += (size_t)z * bA;  a2 += (size_t)z * bA;
    s1 += (size_t)z * bS;  s2 += (size_t)z * bS;
    if (tid < 64) { a1sm[tid] = a1[n0 + tid]; a2sm[tid] = a2[n0 + tid]; }
    uint32_t abase = smem_u32(Asm), bbase = smem_u32(Bsm);

    auto issue = [&](int t, int buf) {
        int k0 = t * 16;
#pragma unroll
        for (int u = 0; u < 2; u++) {
            int idx = tid + 256 * u;
            int r = idx >> 2, q = idx & 3;
            CP_ASYNC16(abase + (uint32_t)(buf * 128 * SA + r * SA + q * 4) * 4,
                       A + (size_t)(i0 + r) * FIN + k0 + q * 4);
        }
        {
            int r = tid >> 4, q = tid & 15;
            CP_ASYNC16(bbase + (uint32_t)(buf * 16 * SB + r * SB + q * 4) * 4,
                       B + (size_t)(k0 + r) * NB + n0 + q * 4);
        }
        CP_COMMIT();
    };

    float acc[8][4] = {};
    issue(0, 0);
    for (int t = 0; t < 32; t++) {
        if (t + 1 < 32) { issue(t + 1, (t + 1) & 1); CP_WAIT(1); }
        else            { CP_WAIT(0); }
        __syncthreads();
        const float* As = &Asm[t & 1][0];
        const float* Bs = &Bsm[t & 1][0];
#pragma unroll
        for (int ks = 0; ks < 2; ks++) {
            int k8 = ks * 8;
            float af[4];
            af[0] = As[(16 * wid + g) * SA + k8 + c];
            af[1] = As[(16 * wid + 8 + g) * SA + k8 + c];
            af[2] = As[(16 * wid + g) * SA + k8 + c + 4];
            af[3] = As[(16 * wid + 8 + g) * SA + k8 + c + 4];
#pragma unroll
            for (int f = 0; f < 8; f++) {
                float b0 = Bs[(k8 + c) * SB + 8 * f + g];
                float b1 = Bs[(k8 + c + 4) * SB + 8 * f + g];
                mma_tf32(acc[f], af, b0, b1);
            }
        }
        __syncthreads();
    }

    int rA = i0 + 16 * wid + g, rB = rA + 8;
#pragma unroll
    for (int f = 0; f < 8; f++) {
        float p0 = __shfl_xor_sync(~0u, acc[f][0], 4);
        float p1 = __shfl_xor_sync(~0u, acc[f][1], 4);
        float p2 = __shfl_xor_sync(~0u, acc[f][2], 4);
        float p3 = __shfl_xor_sync(~0u, acc[f][3], 4);
        if (!(g & 1)) {
            int col = n0 + 8 * f + 2 * c;
            uint2 v0; v0.x = packbf(acc[f][0], p0); v0.y = packbf(acc[f][1], p1);
            *(uint2*)&Vb[(size_t)(rA >> 1) * NB + col] = v0;
            uint2 v1; v1.x = packbf(acc[f][2], p2); v1.y = packbf(acc[f][3], p3);
            *(uint2*)&Vb[(size_t)(rB >> 1) * NB + col] = v1;
        }
    }
    float u1 = 0.f, u2 = 0.f, w1 = 0.f, w2 = 0.f;
#pragma unroll
    for (int f = 0; f < 8; f++) {
        int col = 8 * f + 2 * c;
        u1 += acc[f][0] * a1sm[col] + acc[f][1] * a1sm[col + 1];
        u2 += acc[f][0] * a2sm[col] + acc[f][1] * a2sm[col + 1];
        w1 += acc[f][2] * a1sm[col] + acc[f][3] * a1sm[col + 1];
        w2 += acc[f][2] * a2sm[col] + acc[f][3] * a2sm[col + 1];
    }
    u1 += __shfl_xor_sync(~0u, u1, 1); u1 += __shfl_xor_sync(~0u, u1, 2);
    u2 += __shfl_xor_sync(~0u, u2, 1); u2 += __shfl_xor_sync(~0u, u2, 2);
    w1 += __shfl_xor_sync(~0u, w1, 1); w1 += __shfl_xor_sync(~0u, w1, 2);
    w2 += __shfl_xor_sync(~0u, w2, 1); w2 += __shfl_xor_sync(~0u, w2, 2);
    if (c == 0) {
        if (L1) {
            s1[rA] = u1; s2[rA] = u2; s1[rB] = w1; s2[rB] = w2;
            atomicMax(&enc[z], encf(u2));
            atomicMax(&enc[z], encf(w2));
        } else {
            atomicAdd(&s1[rA], u1); atomicAdd(&s2[rA], u2);
            atomicAdd(&s1[rB], w1); atomicAdd(&s2[rB], w2);
        }
    }
}

// =================== fused attention: table-driven P + bf16 mma ===================
// MODE 0 (layer1): blockIdx.z = head; out = hbuf (div + elu), cols z*64.
// MODE 1 (layer2): blockIdx.z = jsplit; partial num/den, cols blockIdx.y*128+colofs.
template<int NCOLS, int RPB, int TT, int MODE>
__global__ void __launch_bounds__(256) attn_mma(
    const uint32_t* __restrict__ Vb, int vrstride, int vzstride,
    const float* __restrict__ s1g, const float* __restrict__ s2g,
    const float* __restrict__ Eag, const float* __restrict__ Ebg,
    const uint32_t* __restrict__ Ftg, const uint32_t* __restrict__ adjb,
    float* __restrict__ outp, float* __restrict__ denp)
{
    constexpr int NFRAG = 8;
    constexpr int SVP = NCOLS + 8;
    constexpr int ROWG = RPB / 16;
    extern __shared__ uint32_t vsm[];

    int tid = threadIdx.x, wid = tid >> 5, lane = tid & 31;
    int g = lane >> 2, c = lane & 3;
    int z = blockIdx.z;
    int aofs = (MODE == 0) ? z * N_NODES : 0;
    const float* s1p = s1g + aofs;
    const float* s2p = s2g + aofs;
    const float* Eap = Eag + aofs;
    const float* Ebp = Ebg + aofs;
    const uint32_t* Ftp = Ftg + aofs;
    const uint32_t* vsrc = Vb + ((MODE == 0) ? (size_t)z * vzstride
                                             : (size_t)blockIdx.y * NCOLS);
    int jbase = (MODE == 1) ? z * 2048 : 0;
    int prbase = jbase >> 1;

    int i0 = blockIdx.x * RPB;
    int rowgrp = wid % ROWG, colgrp = wid / ROWG;
    int colofs = colgrp * 64;
    int r0 = i0 + rowgrp * 16 + g;

    float thA = -s1p[r0], thB = -s1p[r0 + 8];
    float EaA = Eap[r0], EbA = Ebp[r0];
    float EaB = Eap[r0 + 8], EbB = Ebp[r0 + 8];
    const uint2* adjrow0 = (const uint2*)(adjb + (size_t)r0 * (N_NODES / 32));
    const uint2* adjrow1 = (const uint2*)(adjb + (size_t)(r0 + 8) * (N_NODES / 32));

    float acc[NFRAG][4];
#pragma unroll
    for (int f = 0; f < NFRAG; f++)
#pragma unroll
        for (int q = 0; q < 4; q++) acc[f][q] = 0.f;
    uint32_t aPn[4][4];
    float dacc0 = 0.f, dacc1 = 0.f;
    uint32_t vbase = smem_u32(vsm);

    auto issueV = [&](int t) {
        int buf = t % 3;
        int pr0 = prbase + t * 32;
#pragma unroll
        for (int u = 0; u < (32 * NCOLS / 4) / 256; u++) {
            int idx = tid + 256 * u;
            int jp = idx / (NCOLS / 4);
            int q  = idx % (NCOLS / 4);
            uint32_t dst = vbase + (uint32_t)(buf * 32 * SVP + jp * SVP + q * 4) * 4;
            CP_ASYNC16(dst, vsrc + (size_t)(pr0 + jp) * vrstride + q * 4);
        }
    };
    auto computeP = [&](int j0) {   // absolute j
        uint2 w0 = adjrow0[j0 >> 6];
        uint2 w1 = adjrow1[j0 >> 6];
        unsigned long long bm0 = (unsigned long long)w0.x | ((unsigned long long)w0.y << 32);
        unsigned long long bm1 = (unsigned long long)w1.x | ((unsigned long long)w1.y << 32);
        uint32_t l0 = (uint32_t)(bm0 >> (2 * c)), h0 = ((uint32_t)(bm0 >> 32)) >> (2 * c);
        uint32_t l1 = (uint32_t)(bm1 >> (2 * c)), h1 = ((uint32_t)(bm1 >> 32)) >> (2 * c);
#pragma unroll
        for (int ks = 0; ks < 4; ks++) {
            uint32_t wA = (ks < 2) ? l0 : h0;
            uint32_t wB = (ks < 2) ? l1 : h1;
            const int sh = (ks & 1) * 16;
            int base = 16 * ks + 2 * c;
            float2 sA = *(const float2*)(s2p + j0 + base);
            float2 sB = *(const float2*)(s2p + j0 + base + 8);
            uint2  fA = *(const uint2*)(Ftp + j0 + base);
            uint2  fB = *(const uint2*)(Ftp + j0 + base + 8);
            float Fa0 = __uint_as_float(fA.x << 16), Fb0 = __uint_as_float(fA.x & 0xffff0000u);
            float Fa1 = __uint_as_float(fA.y << 16), Fb1 = __uint_as_float(fA.y & 0xffff0000u);
            float Fa2 = __uint_as_float(fB.x << 16), Fb2 = __uint_as_float(fB.x & 0xffff0000u);
            float Fa3 = __uint_as_float(fB.y << 16), Fb3 = __uint_as_float(fB.y & 0xffff0000u);
            bool cA0 = sA.x >= thA, cA1 = sA.y >= thA, cA2 = sB.x >= thA, cA3 = sB.y >= thA;
            bool cB0 = sA.x >= thB, cB1 = sA.y >= thB, cB2 = sB.x >= thB, cB3 = sB.y >= thB;
            float p00 = ((wA >> (sh + 0)) & 1u) ? (cA0 ? EaA : EbA) * (cA0 ? Fa0 : Fb0) : 0.f;
            float p01 = ((wA >> (sh + 1)) & 1u) ? (cA1 ? EaA : EbA) * (cA1 ? Fa1 : Fb1) : 0.f;
            float p02 = ((wA >> (sh + 8)) & 1u) ? (cA2 ? EaA : EbA) * (cA2 ? Fa2 : Fb2) : 0.f;
            float p03 = ((wA >> (sh + 9)) & 1u) ? (cA3 ? EaA : EbA) * (cA3 ? Fa3 : Fb3) : 0.f;
            float p10 = ((wB >> (sh + 0)) & 1u) ? (cB0 ? EaB : EbB) * (cB0 ? Fa0 : Fb0) : 0.f;
            float p11 = ((wB >> (sh + 1)) & 1u) ? (cB1 ? EaB : EbB) * (cB1 ? Fa1 : Fb1) : 0.f;
            float p12 = ((wB >> (sh + 8)) & 1u) ? (cB2 ? EaB : EbB) * (cB2 ? Fa2 : Fb2) : 0.f;
            float p13 = ((wB >> (sh + 9)) & 1u) ? (cB3 ? EaB : EbB) * (cB3 ? Fa3 : Fb3) : 0.f;
            dacc0 += (p00 + p01) + (p02 + p03);
            dacc1 += (p10 + p11) + (p12 + p13);
            aPn[ks][0] = packbf(p00, p01);
            aPn[ks][1] = packbf(p10, p11);
            aPn[ks][2] = packbf(p02, p03);
            aPn[ks][3] = packbf(p12, p13);
        }
    };

    issueV(0); CP_COMMIT();
    issueV(1); CP_COMMIT();
    computeP(jbase);

    for (int t = 0; t < TT; t++) {
        CP_WAIT(1);
        __syncthreads();
        if (t + 2 < TT) issueV(t + 2);
        CP_COMMIT();
        const uint32_t* vb = vsm + (t % 3) * 32 * SVP;
#pragma unroll
        for (int f = 0; f < NFRAG; f++) {
            int col = colofs + 8 * f + g;
#pragma unroll
            for (int ks = 0; ks < 4; ks++) {
                uint32_t b0 = vb[(ks * 8 + c) * SVP + col];
                uint32_t b1 = vb[(ks * 8 + c + 4) * SVP + col];
                mma_bf16(acc[f], aPn[ks], b0, b1);
            }
        }
        if (t + 1 < TT) computeP(jbase + (t + 1) * 64);
    }

    dacc0 += __shfl_xor_sync(~0u, dacc0, 1);
    dacc0 += __shfl_xor_sync(~0u, dacc0, 2);
    dacc1 += __shfl_xor_sync(~0u, dacc1, 1);
    dacc1 += __shfl_xor_sync(~0u, dacc1, 2);

    if (MODE == 0) {
        float dinv0 = 1.0f / dacc0, dinv1 = 1.0f / dacc1;
        float* row0 = outp + (size_t)r0 * (HEADS * HID) + z * 64 + colofs;
        float* row1 = row0 + 8 * (HEADS * HID);
#pragma unroll
        for (int f = 0; f < NFRAG; f++) {
            int col = 8 * f + 2 * c;
            float2 v0, v1;
            v0.x = elu1(acc[f][0] * dinv0); v0.y = elu1(acc[f][1] * dinv0);
            v1.x = elu1(acc[f][2] * dinv1); v1.y = elu1(acc[f][3] * dinv1);
            *(float2*)&row0[col] = v0;
            *(float2*)&row1[col] = v1;
        }
    } else {
        float* num = outp + (size_t)z * (N_NODES * FOUT);
        int outc = blockIdx.y * 128 + colofs;
        float* row0 = num + (size_t)r0 * FOUT + outc;
        float* row1 = row0 + 8 * FOUT;
#pragma unroll
        for (int f = 0; f < NFRAG; f++) {
            int col = 8 * f + 2 * c;
            float2 v0, v1;
            v0.x = acc[f][0]; v0.y = acc[f][1];
            v1.x = acc[f][2]; v1.y = acc[f][3];
            *(float2*)&row0[col] = v0;
            *(float2*)&row1[col] = v1;
        }
        if (c == 0 && colgrp == 0 && blockIdx.y == 0) {
            denp[z * N_NODES + r0] = dacc0;
            denp[z * N_NODES + r0 + 8] = dacc1;
        }
    }
}

// ---------------- combine partials + elu + log_softmax ----------------
__global__ __launch_bounds__(256) void final_kernel(
    const float* __restrict__ num, const float* __restrict__ den,
    float* __restrict__ out)
{
    int warp = threadIdx.x >> 5, lane = threadIdx.x & 31;
    int row = blockIdx.x * 8 + warp;
    const float* n0 = num + (size_t)row * FOUT;
    const float* n1 = n0 + (size_t)N_NODES * FOUT;
    float dinv = 1.0f / (den[row] + den[N_NODES + row]);
    float v[8];
    float mx = -1e30f;
#pragma unroll
    for (int k = 0; k < 8; k++) {
        int idx = lane + k * 32;
        float x = (n0[idx] + n1[idx]) * dinv;
        x = elu1(x);
        v[k] = x;
        mx = fmaxf(mx, x);
    }
#pragma unroll
    for (int o = 16; o > 0; o >>= 1) mx = fmaxf(mx, __shfl_xor_sync(~0u, mx, o));
    float s = 0.f;
#pragma unroll
    for (int k = 0; k < 8; k++) s += fast_exp(v[k] - mx);
#pragma unroll
    for (int o = 16; o > 0; o >>= 1) s += __shfl_xor_sync(~0u, s, o);
    float lse = mx + logf(s);
#pragma unroll
    for (int k = 0; k < 8; k++) out[(size_t)row * FOUT + lane + k * 32] = v[k] - lse;
}

// ---------------- launcher ----------------
extern "C" void kernel_launch(void* const* d_in, const int* in_sizes, int n_in,
                              void* d_out, int out_size)
{
    const float* x        = (const float*)d_in[0];
    const int*   adj      = (const int*)  d_in[1];
    const float* W_heads  = (const float*)d_in[2];
    const float* a1_heads = (const float*)d_in[3];
    const float* a2_heads = (const float*)d_in[4];
    const float* W_out    = (const float*)d_in[5];
    const float* a1_out   = (const float*)d_in[6];
    const float* a2_out   = (const float*)d_in[7];
    float* out = (float*)d_out;

    float *hbuf, *num, *den, *s1, *s2, *s1b, *s2b, *Ea1, *Eb1, *Ea2, *Eb2;
    uint32_t *adjb, *Vb1, *Vb2, *F1, *F2;
    unsigned *enc1;
    cudaGetSymbolAddress((void**)&Vb1,  g_Vb1);
    cudaGetSymbolAddress((void**)&hbuf, g_h);
    cudaGetSymbolAddress((void**)&Vb2,  g_Vb2);
    cudaGetSymbolAddress((void**)&num,  g_num);
    cudaGetSymbolAddress((void**)&den,  g_den);
    cudaGetSymbolAddress((void**)&adjb, g_adjbits);
    cudaGetSymbolAddress((void**)&s1,   g_s1);
    cudaGetSymbolAddress((void**)&s2,   g_s2);
    cudaGetSymbolAddress((void**)&s1b,  g_s1b);
    cudaGetSymbolAddress((void**)&s2b,  g_s2b);
    cudaGetSymbolAddress((void**)&enc1, g_enc1);
    cudaGetSymbolAddress((void**)&Ea1,  g_Ea1);
    cudaGetSymbolAddress((void**)&Eb1,  g_Eb1);
    cudaGetSymbolAddress((void**)&F1,   g_F1);
    cudaGetSymbolAddress((void**)&Ea2,  g_Ea2);
    cudaGetSymbolAddress((void**)&Eb2,  g_Eb2);
    cudaGetSymbolAddress((void**)&F2,   g_F2);

    const int SM1 = 3 * 32 * (HID + 8) * 4;    // 27648
    const int SM2 = 3 * 32 * (128 + 8) * 4;    // 52224
    cudaFuncSetAttribute(attn_mma<HID, 128, 64, 0>,
                         cudaFuncAttributeMaxDynamicSharedMemorySize, SM1);
    cudaFuncSetAttribute(attn_mma<128, 64, 32, 1>,
                         cudaFuncAttributeMaxDynamicSharedMemorySize, SM2);

    // 0: adj bitmask + zeroing
    pack_adj<<<(N_NODES * (N_NODES / 32)) / 256, 256>>>(adj, adjb, s1b, s2b, enc1);
    // 1: layer-1 GEMM (+V bf16 pairs, s1/s2, s2max)
    gemm_tc<1><<<dim3(N_NODES / 128, 1, HEADS), 256>>>(
        x, W_heads, Vb1, a1_heads, a2_heads, s1, s2, enc1,
        HID, FIN * HID, (N_NODES / 2) * HID, HID, N_NODES);
    // 2: layer-1 factor tables
    prep1<<<(HEADS * N_NODES) / 256, 256>>>(s1, s2, enc1, Ea1, Eb1, F1);
    // 3: layer-1 attention (<- profiled slot)
    attn_mma<HID, 128, 64, 0><<<dim3(N_NODES / 128, 1, HEADS), 256, SM1>>>(
        Vb1, HID, (N_NODES / 2) * HID, s1, s2, Ea1, Eb1, F1, adjb, hbuf, nullptr);
    // 4: layer-2 GEMM
    gemm_tc<0><<<dim3(N_NODES / 128, FOUT / 64, 1), 256>>>(
        hbuf, W_out, Vb2, a1_out, a2_out, s1b, s2b, enc1, FOUT, 0, 0, 0, 0);
    // 5: layer-2 max + tables
    max2_prep2<<<1, 256>>>(s1b, s2b, Ea2, Eb2, F2);
    // 6: layer-2 attention (j-split partials)
    attn_mma<128, 64, 32, 1><<<dim3(N_NODES / 64, 2, 2), 256, SM2>>>(
        Vb2, FOUT, 0, s1b, s2b, Ea2, Eb2, F2, adjb, num, den);
    // 7: combine + elu + log_softmax
    final_kernel<<<N_NODES / 8, 256>>>(num, den, out);
}